// round 6
// baseline (speedup 1.0000x reference)
#include <cuda_runtime.h>
#include <cstdint>

#define Tn  512
#define Bn  1024
#define Sn  64
#define An  16
#define Hn  128
#define TBn (Tn*Bn)

typedef unsigned long long ull;

// ---------------------------------------------------------------------------
// Scratch (__device__ globals)
// ---------------------------------------------------------------------------
__device__ float g_gx[(size_t)TBn * 384];      // gate preactivations [T*B, 3H]
__device__ float g_hidden[(size_t)TBn * Hn];   // hidden states [T*B, H]

// Pre-transposed, pre-duplicated ull weight images (entry = {w,w} f32x2)
#define WU 132                                  // ull stride per k-row
__device__ ull g_w1t[64 * WU];                  // [k][j]
__device__ ull g_w2t[128 * WU];
__device__ ull g_wiht[3][128 * WU];

// ---------------------------------------------------------------------------
// f32x2 helpers
// ---------------------------------------------------------------------------
__device__ __forceinline__ ull pack2(float lo, float hi) {
    ull r;
    asm("mov.b64 %0, {%1, %2};" : "=l"(r)
        : "r"(__float_as_uint(lo)), "r"(__float_as_uint(hi)));
    return r;
}
__device__ __forceinline__ ull dup2(float v) { return pack2(v, v); }
__device__ __forceinline__ void unpack2(ull p, float& lo, float& hi) {
    unsigned int a, b;
    asm("mov.b64 {%0, %1}, %2;" : "=r"(a), "=r"(b) : "l"(p));
    lo = __uint_as_float(a); hi = __uint_as_float(b);
}
__device__ __forceinline__ void fma2(ull& d, ull a, ull b) {
    asm("fma.rn.f32x2 %0, %1, %2, %3;" : "=l"(d) : "l"(a), "l"(b), "l"(d));
}
__device__ __forceinline__ float tanh_fast(float x) {
    float y; asm("tanh.approx.f32 %0, %1;" : "=f"(y) : "f"(x)); return y;
}
__device__ __forceinline__ float sigmoid_fast(float x) {
    return fmaf(0.5f, tanh_fast(0.5f * x), 0.5f);
}

// ---------------------------------------------------------------------------
// Prep: W -> transposed ull-dup images (one tiny kernel, runs each launch)
// ---------------------------------------------------------------------------
__global__ void prep_kernel(const float* __restrict__ W1, const float* __restrict__ W2,
                            const float* __restrict__ Wih)
{
    int gs = blockDim.x * gridDim.x;
    int g0 = blockIdx.x * blockDim.x + threadIdx.x;
    for (int i = g0; i < 128 * 64; i += gs) {
        int j = i >> 6, k = i & 63;
        g_w1t[k * WU + j] = dup2(W1[i]);
    }
    for (int i = g0; i < 128 * 128; i += gs) {
        int j = i >> 7, k = i & 127;
        g_w2t[k * WU + j] = dup2(W2[i]);
    }
    for (int i = g0; i < 3 * 128 * 128; i += gs) {
        int j = i >> 7, k = i & 127;
        g_wiht[j >> 7][k * WU + (j & 127)] = dup2(Wih[i]);
    }
}

// ---------------------------------------------------------------------------
// Encoder: fused x -> h1 -> h2 -> gx.  256 threads, 128 rows/block, 1 blk/SM.
// rc = tid&15 owns rows rc*8..+7 ; cc = tid>>4 owns cols cc*8..+7.
// aT[k][row] stride 132 floats; Wt2[k][col] ull (dup pairs) stride 132,
// streamed from global images in 64-k chunks.
// ---------------------------------------------------------------------------
#define EAS 132

__device__ __forceinline__ void gemm64(const float* __restrict__ ap,
                                       const ull* __restrict__ wp,
                                       ull acc[4][8])
{
    #pragma unroll 2
    for (int k = 0; k < 64; k++) {
        ulonglong2 aA = *(const ulonglong2*)(ap + k * EAS);      // rows 01,23
        ulonglong2 aB = *(const ulonglong2*)(ap + k * EAS + 4);  // rows 45,67
        ulonglong2 w01 = *(const ulonglong2*)(wp + k * WU);
        ulonglong2 w23 = *(const ulonglong2*)(wp + k * WU + 2);
        ulonglong2 w45 = *(const ulonglong2*)(wp + k * WU + 4);
        ulonglong2 w67 = *(const ulonglong2*)(wp + k * WU + 6);
        ull a[4] = {aA.x, aA.y, aB.x, aB.y};
        ull w[8] = {w01.x, w01.y, w23.x, w23.y, w45.x, w45.y, w67.x, w67.y};
        #pragma unroll
        for (int c = 0; c < 8; c++) {
            fma2(acc[0][c], a[0], w[c]);
            fma2(acc[1][c], a[1], w[c]);
            fma2(acc[2][c], a[2], w[c]);
            fma2(acc[3][c], a[3], w[c]);
        }
    }
}

__device__ __forceinline__ void stage_w(ull* __restrict__ dst,
                                        const ull* __restrict__ src, int tid)
{
    const uint4* s = (const uint4*)src;
    uint4* d = (uint4*)dst;
    #pragma unroll 4
    for (int i = tid; i < 64 * WU / 2; i += 256) d[i] = s[i];
}

__device__ __forceinline__ void init_acc(ull acc[4][8], const float* bv)
{
    #pragma unroll
    for (int c = 0; c < 8; c++) {
        ull bb = dup2(bv[c]);
        #pragma unroll
        for (int p = 0; p < 4; p++) acc[p][c] = bb;
    }
}

__device__ __forceinline__ void store_relu(float* __restrict__ dst,
                                           int rc, int cc, ull acc[4][8])
{
    #pragma unroll
    for (int c = 0; c < 8; c++) {
        int col = cc * 8 + c;
        float v[8];
        unpack2(acc[0][c], v[0], v[1]); unpack2(acc[1][c], v[2], v[3]);
        unpack2(acc[2][c], v[4], v[5]); unpack2(acc[3][c], v[6], v[7]);
        #pragma unroll
        for (int i = 0; i < 8; i++) v[i] = fmaxf(v[i], 0.f);
        *(float4*)&dst[col * EAS + rc * 8]     = make_float4(v[0], v[1], v[2], v[3]);
        *(float4*)&dst[col * EAS + rc * 8 + 4] = make_float4(v[4], v[5], v[6], v[7]);
    }
}

__global__ void __launch_bounds__(256, 1) encoder_kernel(
    const float* __restrict__ x,
    const float* __restrict__ b1, const float* __restrict__ b2,
    const float* __restrict__ bih)
{
    extern __shared__ char smc[];
    ull*   Wt2 = (ull*)smc;                         // 64*132 ull = 67584 B
    float* h1T = (float*)(smc + 67584);             // 128*132 f  = 67584 B
    float* h2T = (float*)(smc + 135168);            // 128*132 f
    float* xT  = h2T;                               // 64*132 aliased

    int tid = threadIdx.x;
    int rc  = tid & 15;
    int cc  = tid >> 4;
    size_t base = (size_t)blockIdx.x * 128;

    // stage xT (transposed) + W1 image
    for (int idx = tid; idx < 128 * 64; idx += 256) {
        int r = idx >> 6, k = idx & 63;
        xT[k * EAS + r] = x[(base + r) * 64 + k];
    }
    stage_w(Wt2, g_w1t, tid);
    __syncthreads();

    ull acc[4][8];
    float bv[8];

    // ---- Phase A: h1 = relu(x @ W1^T + b1), K=64 ----
    #pragma unroll
    for (int c = 0; c < 8; c++) bv[c] = b1[cc * 8 + c];
    init_acc(acc, bv);
    gemm64(xT + rc * 8, Wt2 + cc * 8, acc);
    store_relu(h1T, rc, cc, acc);

    // ---- Phase B: h2 = relu(h1 @ W2^T + b2), K=128 (2 chunks) ----
    #pragma unroll
    for (int c = 0; c < 8; c++) bv[c] = b2[cc * 8 + c];
    init_acc(acc, bv);
    #pragma unroll 1
    for (int h = 0; h < 2; h++) {
        __syncthreads();                       // h1T visible / Wt2 reads done
        stage_w(Wt2, g_w2t + h * 64 * WU, tid);
        __syncthreads();
        gemm64(h1T + (h * 64) * EAS + rc * 8, Wt2 + cc * 8, acc);
    }
    store_relu(h2T, rc, cc, acc);              // xT dead; sync comes in phase C

    // ---- Phase C: gx = h2 @ Wih^T + bih, 3 passes x 2 chunks ----
    #pragma unroll 1
    for (int pp = 0; pp < 3; pp++) {
        #pragma unroll
        for (int c = 0; c < 8; c++) bv[c] = bih[pp * 128 + cc * 8 + c];
        init_acc(acc, bv);
        #pragma unroll 1
        for (int h = 0; h < 2; h++) {
            __syncthreads();                   // h2T visible / Wt2 reads done
            stage_w(Wt2, g_wiht[pp] + h * 64 * WU, tid);
            __syncthreads();
            gemm64(h2T + (h * 64) * EAS + rc * 8, Wt2 + cc * 8, acc);
        }
        // store 32B contiguous per (thread,row): full-sector writes
        #pragma unroll
        for (int i = 0; i < 8; i++) {
            float v[8];
            #pragma unroll
            for (int c = 0; c < 8; c++) {
                float lo, hi;
                unpack2(acc[i >> 1][c], lo, hi);
                v[c] = (i & 1) ? hi : lo;
            }
            size_t row = base + rc * 8 + i;
            float* dst = &g_gx[row * 384 + pp * 128 + cc * 8];
            *(float4*)dst       = make_float4(v[0], v[1], v[2], v[3]);
            *(float4*)(dst + 4) = make_float4(v[4], v[5], v[6], v[7]);
        }
    }
}

// ---------------------------------------------------------------------------
// GRU scan: 128 blocks x 8 batch rows, 256 threads (c = col, kh = k-half).
// w planes [g][k][c] stride 130 (scalar LDS, conflict-free).
// hT[k][r] stride 12, double-buffered (LDS.128 broadcast, rows pre-paired).
// ---------------------------------------------------------------------------
#define WP 130

__global__ void __launch_bounds__(256, 1) scan_kernel(
    const float* __restrict__ done, const float* __restrict__ gru0,
    const float* __restrict__ Whh, const float* __restrict__ bhh,
    float* __restrict__ out)
{
    extern __shared__ float sm[];
    float* wsm = sm;                        // 3*128*130 = 49920 floats
    float* hb  = wsm + 3 * 128 * WP;        // 2*128*12  =  3072
    float* red = hb + 2 * 128 * 12;         // 128*25    =  3200

    int tid = threadIdx.x;
    int c   = tid & 127;
    int kh  = tid >> 7;
    int b0  = blockIdx.x << 3;

    // stage Whh -> [g][k][c] (coalesced read, strided STS once)
    for (int idx = tid; idx < 384 * 128; idx += 256) {
        int k = idx & 127, j = idx >> 7;
        int g = j >> 7, co = j & 127;
        wsm[g * 128 * WP + k * WP + co] = Whh[j * 128 + k];
    }
    // initial h (t=0 mask folded), hT[k][r]
    for (int idx = tid; idx < 8 * 128; idx += 256) {
        int r = idx >> 7, f = idx & 127;
        hb[f * 12 + r] = gru0[(b0 + r) * 128 + f] * (1.f - done[b0 + r]);
    }
    __syncthreads();

    const float* w0 = wsm + c;
    const float* w1 = wsm + 128 * WP + c;
    const float* w2 = wsm + 256 * WP + c;

    float br = bhh[c], bz = bhh[c + 128], bn = bhh[c + 256];

    float gx0[8], gx1[8], gx2[8];
    if (kh == 0) {
        #pragma unroll
        for (int r = 0; r < 8; r++) {
            size_t row = (size_t)(b0 + r);
            gx0[r] = g_gx[row * 384 + c];
            gx1[r] = g_gx[row * 384 + 128 + c];
            gx2[r] = g_gx[row * 384 + 256 + c];
        }
    }

    int cur = 0;
    for (int t = 0; t < Tn; t++) {
        // prefetch next gx + done (kh0 only, hidden under k-loop)
        float gn0[8], gn1[8], gn2[8], dn[8];
        if (kh == 0) {
            int tnx = (t + 1 < Tn) ? (t + 1) : t;
            #pragma unroll
            for (int r = 0; r < 8; r++) {
                size_t row = (size_t)tnx * Bn + b0 + r;
                gn0[r] = g_gx[row * 384 + c];
                gn1[r] = g_gx[row * 384 + 128 + c];
                gn2[r] = g_gx[row * 384 + 256 + c];
                dn[r] = (t + 1 < Tn) ? done[(size_t)(t + 1) * Bn + b0 + r] : 0.f;
            }
        }

        const float* hbc = hb + cur * 1536;
        ull aR[4], aZ[4], aN[4];
        #pragma unroll
        for (int p = 0; p < 4; p++) { aR[p] = 0ull; aZ[p] = 0ull; aN[p] = 0ull; }

        const float* hk = hbc + kh * 64 * 12;
        const float* wk0 = w0 + kh * 64 * WP;
        const float* wk1 = w1 + kh * 64 * WP;
        const float* wk2 = w2 + kh * 64 * WP;
        #pragma unroll 4
        for (int k = 0; k < 64; k++) {
            ulonglong2 h01 = *(const ulonglong2*)(hk + k * 12);      // rows 0-3
            ulonglong2 h23 = *(const ulonglong2*)(hk + k * 12 + 4);  // rows 4-7
            ull wr = dup2(wk0[k * WP]);
            ull wz = dup2(wk1[k * WP]);
            ull wn = dup2(wk2[k * WP]);
            fma2(aR[0], h01.x, wr); fma2(aR[1], h01.y, wr);
            fma2(aR[2], h23.x, wr); fma2(aR[3], h23.y, wr);
            fma2(aZ[0], h01.x, wz); fma2(aZ[1], h01.y, wz);
            fma2(aZ[2], h23.x, wz); fma2(aZ[3], h23.y, wz);
            fma2(aN[0], h01.x, wn); fma2(aN[1], h01.y, wn);
            fma2(aN[2], h23.x, wn); fma2(aN[3], h23.y, wn);
        }

        float pr[8], pz[8], pn[8];
        #pragma unroll
        for (int p = 0; p < 4; p++) {
            unpack2(aR[p], pr[2 * p], pr[2 * p + 1]);
            unpack2(aZ[p], pz[2 * p], pz[2 * p + 1]);
            unpack2(aN[p], pn[2 * p], pn[2 * p + 1]);
        }

        if (kh == 1) {
            #pragma unroll
            for (int r = 0; r < 8; r++) {
                red[c * 25 + r]      = pr[r];
                red[c * 25 + 8 + r]  = pz[r];
                red[c * 25 + 16 + r] = pn[r];
            }
        }
        __syncthreads();

        if (kh == 0) {
            float ho[8];
            ulonglong2 h01 = *(const ulonglong2*)(hbc + c * 12);
            ulonglong2 h23 = *(const ulonglong2*)(hbc + c * 12 + 4);
            unpack2(h01.x, ho[0], ho[1]); unpack2(h01.y, ho[2], ho[3]);
            unpack2(h23.x, ho[4], ho[5]); unpack2(h23.y, ho[6], ho[7]);

            float* hnxt = hb + (cur ^ 1) * 1536;
            float hnv[8];
            #pragma unroll
            for (int r = 0; r < 8; r++) {
                float sr = pr[r] + red[c * 25 + r]      + br + gx0[r];
                float sz = pz[r] + red[c * 25 + 8 + r]  + bz + gx1[r];
                float sn = pn[r] + red[c * 25 + 16 + r] + bn;
                float rg = sigmoid_fast(sr);
                float zg = sigmoid_fast(sz);
                float ng = tanh_fast(gx2[r] + rg * sn);
                float hnew = (1.f - zg) * ng + zg * ho[r];
                hnv[r] = hnew;
                g_hidden[((size_t)t * Bn + b0 + r) * Hn + c] = hnew;
                gx0[r] = gn0[r]; gx1[r] = gn1[r]; gx2[r] = gn2[r];
            }
            *(float4*)&hnxt[c * 12] = make_float4(
                hnv[0] * (1.f - dn[0]), hnv[1] * (1.f - dn[1]),
                hnv[2] * (1.f - dn[2]), hnv[3] * (1.f - dn[3]));
            *(float4*)&hnxt[c * 12 + 4] = make_float4(
                hnv[4] * (1.f - dn[4]), hnv[5] * (1.f - dn[5]),
                hnv[6] * (1.f - dn[6]), hnv[7] * (1.f - dn[7]));
            if (t == Tn - 1) {
                #pragma unroll
                for (int r = 0; r < 8; r++)
                    out[(size_t)TBn * 3 + (b0 + r) * Hn + c] = hnv[r];
            }
        }
        __syncthreads();
        cur ^= 1;
    }
}

// ---------------------------------------------------------------------------
// Heads: 256 rows/block, thread-per-row.
// ---------------------------------------------------------------------------
__global__ void __launch_bounds__(256, 1) heads_kernel(
    const int* __restrict__ action,
    const float* __restrict__ Wa, const float* __restrict__ ba,
    const float* __restrict__ Wc, const float* __restrict__ bc,
    float* __restrict__ out)
{
    extern __shared__ float sm[];
    const int OFF_WA = 256 * 129;
    const int OFF_WC = OFF_WA + 16 * 128;
    int tid  = threadIdx.x;
    int base = blockIdx.x << 8;

    for (int idx = tid; idx < 256 * 128; idx += 256) {
        int r = idx >> 7, k = idx & 127;
        sm[r * 129 + k] = g_hidden[(size_t)(base + r) * 128 + k];
    }
    for (int idx = tid; idx < 16 * 128; idx += 256) sm[OFF_WA + idx] = Wa[idx];
    if (tid < 128) sm[OFF_WC + tid] = Wc[tid];
    __syncthreads();

    float l[16];
    #pragma unroll
    for (int j = 0; j < 16; j++) l[j] = ba[j];
    float v = bc[0];
    const float* hrow = &sm[tid * 129];
    #pragma unroll 4
    for (int k = 0; k < 128; k++) {
        float hv = hrow[k];
        #pragma unroll
        for (int j = 0; j < 16; j++) l[j] += sm[OFF_WA + j * 128 + k] * hv;
        v += sm[OFF_WC + k] * hv;
    }
    float mx = l[0];
    #pragma unroll
    for (int j = 1; j < 16; j++) mx = fmaxf(mx, l[j]);
    float se = 0.f, pl = 0.f;
    #pragma unroll
    for (int j = 0; j < 16; j++) {
        float e = __expf(l[j] - mx);
        se += e; pl += e * l[j];
    }
    float lse = mx + __logf(se);
    int row = base + tid;
    int a = action[row];
    float la = 0.f;
    #pragma unroll
    for (int j = 0; j < 16; j++) la = (a == j) ? l[j] : la;
    out[(size_t)row * 3 + 0] = la - lse;
    out[(size_t)row * 3 + 1] = lse - pl / se;
    out[(size_t)row * 3 + 2] = v;
}

// ---------------------------------------------------------------------------
extern "C" void kernel_launch(void* const* d_in, const int* in_sizes, int n_in,
                              void* d_out, int out_size)
{
    const float* x    = (const float*)d_in[0];
    const float* done = (const float*)d_in[1];
    const int*   act  = (const int*)  d_in[2];
    const float* gru  = (const float*)d_in[3];
    const float* W1   = (const float*)d_in[4];
    const float* b1   = (const float*)d_in[5];
    const float* W2   = (const float*)d_in[6];
    const float* b2   = (const float*)d_in[7];
    const float* Wih  = (const float*)d_in[8];
    const float* bih  = (const float*)d_in[9];
    const float* Whh  = (const float*)d_in[10];
    const float* bhh  = (const float*)d_in[11];
    const float* Wa   = (const float*)d_in[12];
    const float* ba   = (const float*)d_in[13];
    const float* Wc   = (const float*)d_in[14];
    const float* bc   = (const float*)d_in[15];
    float* out = (float*)d_out;

    size_t enc_smem  = 67584 + 2 * 67584;                                        // 202752 B
    size_t scan_smem = (size_t)(3 * 128 * WP + 2 * 128 * 12 + 128 * 25) * 4;     // 224768 B
    size_t head_smem = (size_t)(256 * 129 + 16 * 128 + 128) * sizeof(float);     // 140800 B

    cudaFuncSetAttribute(encoder_kernel, cudaFuncAttributeMaxDynamicSharedMemorySize, (int)enc_smem);
    cudaFuncSetAttribute(scan_kernel,    cudaFuncAttributeMaxDynamicSharedMemorySize, (int)scan_smem);
    cudaFuncSetAttribute(heads_kernel,   cudaFuncAttributeMaxDynamicSharedMemorySize, (int)head_smem);

    prep_kernel<<<64, 256>>>(W1, W2, Wih);
    encoder_kernel<<<TBn / 128, 256, enc_smem>>>(x, b1, b2, bih);
    scan_kernel<<<128, 256, scan_smem>>>(done, gru, Whh, bhh, out);
    heads_kernel<<<TBn / 256, 256, head_smem>>>(act, Wa, ba, Wc, bc, out);
}

// round 7
// speedup vs baseline: 1.1302x; 1.1302x over previous
#include <cuda_runtime.h>
#include <cstdint>

#define Tn  512
#define Bn  1024
#define Sn  64
#define An  16
#define Hn  128
#define TBn (Tn*Bn)

typedef unsigned long long ull;

__device__ float g_gx[(size_t)TBn * 384];      // gate preactivations [T*B, 3H]
__device__ float g_hidden[(size_t)TBn * Hn];   // hidden states [T*B, H]

// ---------------------------------------------------------------------------
// f32x2 + fast-math helpers
// ---------------------------------------------------------------------------
__device__ __forceinline__ ull pack2(float lo, float hi) {
    ull r;
    asm("mov.b64 %0, {%1, %2};" : "=l"(r)
        : "r"(__float_as_uint(lo)), "r"(__float_as_uint(hi)));
    return r;
}
__device__ __forceinline__ ull dup2(float v) { return pack2(v, v); }
__device__ __forceinline__ void unpack2(ull p, float& lo, float& hi) {
    unsigned int a, b;
    asm("mov.b64 {%0, %1}, %2;" : "=r"(a), "=r"(b) : "l"(p));
    lo = __uint_as_float(a); hi = __uint_as_float(b);
}
__device__ __forceinline__ void fma2(ull& d, ull a, ull b) {
    asm("fma.rn.f32x2 %0, %1, %2, %3;" : "=l"(d) : "l"(a), "l"(b), "l"(d));
}
__device__ __forceinline__ float tanh_fast(float x) {
    float y; asm("tanh.approx.f32 %0, %1;" : "=f"(y) : "f"(x)); return y;
}
__device__ __forceinline__ float sigmoid_fast(float x) {
    return fmaf(0.5f, tanh_fast(0.5f * x), 0.5f);
}

// ---------------------------------------------------------------------------
// Encoder (R3, best measured): fused x -> h1 -> h2 -> gx.
// 512 threads, 64 rows/block, 2 blocks/SM.
// rg = tid>>6 owns rows rg*8..+7 ; cg = tid&63 owns cols 2cg,2cg+1.
// aT[k][row] stride 68; Wt[k][col] stride 130, streamed in 64-k chunks.
// ---------------------------------------------------------------------------
#define EA  68
#define EWs 130

__device__ __forceinline__ void enc_gemm64(const float* __restrict__ ap,
                                           const float* __restrict__ wp,
                                           ull acc[4][2])
{
    #pragma unroll 4
    for (int k = 0; k < 64; k++) {
        ulonglong2 a01 = *(const ulonglong2*)(ap + k * EA);      // rows (0,1),(2,3)
        ulonglong2 a23 = *(const ulonglong2*)(ap + k * EA + 4);  // rows (4,5),(6,7)
        float2 wv = *(const float2*)(wp + k * EWs);
        ull w0 = dup2(wv.x), w1 = dup2(wv.y);
        fma2(acc[0][0], a01.x, w0); fma2(acc[1][0], a01.y, w0);
        fma2(acc[2][0], a23.x, w0); fma2(acc[3][0], a23.y, w0);
        fma2(acc[0][1], a01.x, w1); fma2(acc[1][1], a01.y, w1);
        fma2(acc[2][1], a23.x, w1); fma2(acc[3][1], a23.y, w1);
    }
}

__global__ void __launch_bounds__(512, 2) encoder_kernel(
    const float* __restrict__ x,
    const float* __restrict__ W1, const float* __restrict__ b1,
    const float* __restrict__ W2, const float* __restrict__ b2,
    const float* __restrict__ Wih, const float* __restrict__ bih)
{
    extern __shared__ float sm[];
    float* Wt  = sm;                    // 64*130  = 8320 floats
    float* h1T = sm + 64 * EWs;         // 128*68  = 8704 floats
    float* h2T = h1T + 128 * EA;        // 128*68
    float* xT  = h2T;                   // 64*68 aliased into h2T region

    int tid = threadIdx.x;
    int cg  = tid & 63;
    int rg  = tid >> 6;
    int base = blockIdx.x * 64;

    for (int idx = tid; idx < 64 * 64; idx += 512) {
        int k = idx & 63, r = idx >> 6;
        xT[k * EA + r] = x[(base + r) * 64 + k];
    }
    for (int idx = tid; idx < 64 * 128; idx += 512) {
        int k = idx & 63, j = idx >> 6;
        Wt[k * EWs + j] = W1[j * 64 + k];
    }
    __syncthreads();

    ull acc[4][2];

    // ---- Phase A: h1 = relu(x @ W1^T + b1) ----
    acc[0][0] = acc[1][0] = acc[2][0] = acc[3][0] = dup2(b1[2 * cg]);
    acc[0][1] = acc[1][1] = acc[2][1] = acc[3][1] = dup2(b1[2 * cg + 1]);
    enc_gemm64(xT + rg * 8, Wt + 2 * cg, acc);
    #pragma unroll
    for (int c01 = 0; c01 < 2; c01++) {
        float v[8];
        unpack2(acc[0][c01], v[0], v[1]); unpack2(acc[1][c01], v[2], v[3]);
        unpack2(acc[2][c01], v[4], v[5]); unpack2(acc[3][c01], v[6], v[7]);
        #pragma unroll
        for (int i = 0; i < 8; i++) v[i] = fmaxf(v[i], 0.f);
        int col = 2 * cg + c01;
        *(float4*)&h1T[col * EA + rg * 8]     = make_float4(v[0], v[1], v[2], v[3]);
        *(float4*)&h1T[col * EA + rg * 8 + 4] = make_float4(v[4], v[5], v[6], v[7]);
    }
    __syncthreads();

    // ---- Phase B: h2 = relu(h1 @ W2^T + b2), K=128 in 2 chunks ----
    acc[0][0] = acc[1][0] = acc[2][0] = acc[3][0] = dup2(b2[2 * cg]);
    acc[0][1] = acc[1][1] = acc[2][1] = acc[3][1] = dup2(b2[2 * cg + 1]);
    #pragma unroll 1
    for (int h = 0; h < 2; h++) {
        for (int idx = tid; idx < 64 * 128; idx += 512) {
            int kl = idx & 63, j = idx >> 6;
            Wt[kl * EWs + j] = W2[j * 128 + h * 64 + kl];
        }
        __syncthreads();
        enc_gemm64(h1T + (h * 64) * EA + rg * 8, Wt + 2 * cg, acc);
        __syncthreads();
    }
    #pragma unroll
    for (int c01 = 0; c01 < 2; c01++) {
        float v[8];
        unpack2(acc[0][c01], v[0], v[1]); unpack2(acc[1][c01], v[2], v[3]);
        unpack2(acc[2][c01], v[4], v[5]); unpack2(acc[3][c01], v[6], v[7]);
        #pragma unroll
        for (int i = 0; i < 8; i++) v[i] = fmaxf(v[i], 0.f);
        int col = 2 * cg + c01;
        *(float4*)&h2T[col * EA + rg * 8]     = make_float4(v[0], v[1], v[2], v[3]);
        *(float4*)&h2T[col * EA + rg * 8 + 4] = make_float4(v[4], v[5], v[6], v[7]);
    }
    __syncthreads();

    // ---- Phase C: gx = h2 @ Wih^T + bih : 3 col passes x 2 k-chunks ----
    #pragma unroll 1
    for (int pp = 0; pp < 3; pp++) {
        acc[0][0] = acc[1][0] = acc[2][0] = acc[3][0] = dup2(bih[pp * 128 + 2 * cg]);
        acc[0][1] = acc[1][1] = acc[2][1] = acc[3][1] = dup2(bih[pp * 128 + 2 * cg + 1]);
        #pragma unroll 1
        for (int h = 0; h < 2; h++) {
            for (int idx = tid; idx < 64 * 128; idx += 512) {
                int kl = idx & 63, j = idx >> 6;
                Wt[kl * EWs + j] = Wih[(pp * 128 + j) * 128 + h * 64 + kl];
            }
            __syncthreads();
            enc_gemm64(h2T + (h * 64) * EA + rg * 8, Wt + 2 * cg, acc);
            __syncthreads();
        }
        #pragma unroll
        for (int p = 0; p < 4; p++) {
            float v0a, v0b, v1a, v1b;
            unpack2(acc[p][0], v0a, v0b);
            unpack2(acc[p][1], v1a, v1b);
            size_t row0 = (size_t)(base + rg * 8 + 2 * p);
            *(float2*)&g_gx[row0 * 384 + pp * 128 + 2 * cg]       = make_float2(v0a, v1a);
            *(float2*)&g_gx[(row0 + 1) * 384 + pp * 128 + 2 * cg] = make_float2(v0b, v1b);
        }
    }
}

// ---------------------------------------------------------------------------
// GRU scan (R6): 128 blocks x 8 batch rows, 256 threads (c = col, kh = k-half).
// w planes [g][k][c] stride 130 (scalar LDS, conflict-free).
// hT[k][r] stride 12, double-buffered (LDS.128 broadcast, rows pre-paired).
// ---------------------------------------------------------------------------
#define WP 130

__global__ void __launch_bounds__(256, 1) scan_kernel(
    const float* __restrict__ done, const float* __restrict__ gru0,
    const float* __restrict__ Whh, const float* __restrict__ bhh,
    float* __restrict__ out)
{
    extern __shared__ float sm[];
    float* wsm = sm;                        // 3*128*130 = 49920 floats
    float* hb  = wsm + 3 * 128 * WP;        // 2*128*12  =  3072
    float* red = hb + 2 * 128 * 12;         // 128*25    =  3200

    int tid = threadIdx.x;
    int c   = tid & 127;
    int kh  = tid >> 7;
    int b0  = blockIdx.x << 3;

    for (int idx = tid; idx < 384 * 128; idx += 256) {
        int k = idx & 127, j = idx >> 7;
        int g = j >> 7, co = j & 127;
        wsm[g * 128 * WP + k * WP + co] = Whh[j * 128 + k];
    }
    for (int idx = tid; idx < 8 * 128; idx += 256) {
        int r = idx >> 7, f = idx & 127;
        hb[f * 12 + r] = gru0[(b0 + r) * 128 + f] * (1.f - done[b0 + r]);
    }
    __syncthreads();

    const float* w0 = wsm + c;
    const float* w1 = wsm + 128 * WP + c;
    const float* w2 = wsm + 256 * WP + c;

    float br = bhh[c], bz = bhh[c + 128], bn = bhh[c + 256];

    float gx0[8], gx1[8], gx2[8];
    if (kh == 0) {
        #pragma unroll
        for (int r = 0; r < 8; r++) {
            size_t row = (size_t)(b0 + r);
            gx0[r] = g_gx[row * 384 + c];
            gx1[r] = g_gx[row * 384 + 128 + c];
            gx2[r] = g_gx[row * 384 + 256 + c];
        }
    }

    int cur = 0;
    for (int t = 0; t < Tn; t++) {
        float gn0[8], gn1[8], gn2[8], dn[8];
        if (kh == 0) {
            int tnx = (t + 1 < Tn) ? (t + 1) : t;
            #pragma unroll
            for (int r = 0; r < 8; r++) {
                size_t row = (size_t)tnx * Bn + b0 + r;
                gn0[r] = g_gx[row * 384 + c];
                gn1[r] = g_gx[row * 384 + 128 + c];
                gn2[r] = g_gx[row * 384 + 256 + c];
                dn[r] = (t + 1 < Tn) ? done[(size_t)(t + 1) * Bn + b0 + r] : 0.f;
            }
        }

        const float* hbc = hb + cur * 1536;
        ull aR[4], aZ[4], aN[4];
        #pragma unroll
        for (int p = 0; p < 4; p++) { aR[p] = 0ull; aZ[p] = 0ull; aN[p] = 0ull; }

        const float* hk  = hbc + kh * 64 * 12;
        const float* wk0 = w0 + kh * 64 * WP;
        const float* wk1 = w1 + kh * 64 * WP;
        const float* wk2 = w2 + kh * 64 * WP;
        #pragma unroll 4
        for (int k = 0; k < 64; k++) {
            ulonglong2 h01 = *(const ulonglong2*)(hk + k * 12);      // rows 0-3
            ulonglong2 h23 = *(const ulonglong2*)(hk + k * 12 + 4);  // rows 4-7
            ull wr = dup2(wk0[k * WP]);
            ull wz = dup2(wk1[k * WP]);
            ull wn = dup2(wk2[k * WP]);
            fma2(aR[0], h01.x, wr); fma2(aR[1], h01.y, wr);
            fma2(aR[2], h23.x, wr); fma2(aR[3], h23.y, wr);
            fma2(aZ[0], h01.x, wz); fma2(aZ[1], h01.y, wz);
            fma2(aZ[2], h23.x, wz); fma2(aZ[3], h23.y, wz);
            fma2(aN[0], h01.x, wn); fma2(aN[1], h01.y, wn);
            fma2(aN[2], h23.x, wn); fma2(aN[3], h23.y, wn);
        }

        float pr[8], pz[8], pn[8];
        #pragma unroll
        for (int p = 0; p < 4; p++) {
            unpack2(aR[p], pr[2 * p], pr[2 * p + 1]);
            unpack2(aZ[p], pz[2 * p], pz[2 * p + 1]);
            unpack2(aN[p], pn[2 * p], pn[2 * p + 1]);
        }

        if (kh == 1) {
            #pragma unroll
            for (int r = 0; r < 8; r++) {
                red[c * 25 + r]      = pr[r];
                red[c * 25 + 8 + r]  = pz[r];
                red[c * 25 + 16 + r] = pn[r];
            }
        }
        __syncthreads();

        if (kh == 0) {
            float ho[8];
            ulonglong2 h01 = *(const ulonglong2*)(hbc + c * 12);
            ulonglong2 h23 = *(const ulonglong2*)(hbc + c * 12 + 4);
            unpack2(h01.x, ho[0], ho[1]); unpack2(h01.y, ho[2], ho[3]);
            unpack2(h23.x, ho[4], ho[5]); unpack2(h23.y, ho[6], ho[7]);

            float* hnxt = hb + (cur ^ 1) * 1536;
            float hnv[8];
            #pragma unroll
            for (int r = 0; r < 8; r++) {
                float sr = pr[r] + red[c * 25 + r]      + br + gx0[r];
                float sz = pz[r] + red[c * 25 + 8 + r]  + bz + gx1[r];
                float sn = pn[r] + red[c * 25 + 16 + r] + bn;
                float rg = sigmoid_fast(sr);
                float zg = sigmoid_fast(sz);
                float ng = tanh_fast(gx2[r] + rg * sn);
                float hnew = (1.f - zg) * ng + zg * ho[r];
                hnv[r] = hnew;
                g_hidden[((size_t)t * Bn + b0 + r) * Hn + c] = hnew;
                gx0[r] = gn0[r]; gx1[r] = gn1[r]; gx2[r] = gn2[r];
            }
            *(float4*)&hnxt[c * 12] = make_float4(
                hnv[0] * (1.f - dn[0]), hnv[1] * (1.f - dn[1]),
                hnv[2] * (1.f - dn[2]), hnv[3] * (1.f - dn[3]));
            *(float4*)&hnxt[c * 12 + 4] = make_float4(
                hnv[4] * (1.f - dn[4]), hnv[5] * (1.f - dn[5]),
                hnv[6] * (1.f - dn[6]), hnv[7] * (1.f - dn[7]));
            if (t == Tn - 1) {
                #pragma unroll
                for (int r = 0; r < 8; r++)
                    out[(size_t)TBn * 3 + (b0 + r) * Hn + c] = hnv[r];
            }
        }
        __syncthreads();
        cur ^= 1;
    }
}

// ---------------------------------------------------------------------------
// Heads (new): thread-per-row, h read directly from global (LDG.128 stream),
// only Wa/Wc/biases in static smem (8.7 KB) -> high occupancy, DRAM-bound.
// ---------------------------------------------------------------------------
__global__ void __launch_bounds__(512, 4) heads_kernel(
    const int* __restrict__ action,
    const float* __restrict__ Wa, const float* __restrict__ ba,
    const float* __restrict__ Wc, const float* __restrict__ bc,
    float* __restrict__ out)
{
    __shared__ float swa[16 * 128];
    __shared__ float swc[128];
    __shared__ float sba[16];
    __shared__ float sbc;

    int tid = threadIdx.x;
    for (int i = tid; i < 16 * 128; i += 512) swa[i] = Wa[i];
    if (tid < 128) swc[tid] = Wc[tid];
    if (tid < 16)  sba[tid] = ba[tid];
    if (tid == 0)  sbc = bc[0];
    __syncthreads();

    size_t row = (size_t)blockIdx.x * 512 + tid;
    const float* hrow = &g_hidden[row * 128];

    float l[16];
    #pragma unroll
    for (int j = 0; j < 16; j++) l[j] = sba[j];
    float v = sbc;

    #pragma unroll 4
    for (int k4 = 0; k4 < 32; k4++) {
        float4 h4 = *(const float4*)(hrow + k4 * 4);
        const float* wa = &swa[k4 * 4];
        #pragma unroll
        for (int j = 0; j < 16; j++) {
            l[j] += wa[j * 128]     * h4.x;
            l[j] += wa[j * 128 + 1] * h4.y;
            l[j] += wa[j * 128 + 2] * h4.z;
            l[j] += wa[j * 128 + 3] * h4.w;
        }
        v += swc[k4 * 4]     * h4.x + swc[k4 * 4 + 1] * h4.y
           + swc[k4 * 4 + 2] * h4.z + swc[k4 * 4 + 3] * h4.w;
    }

    float mx = l[0];
    #pragma unroll
    for (int j = 1; j < 16; j++) mx = fmaxf(mx, l[j]);
    float se = 0.f, pl = 0.f;
    #pragma unroll
    for (int j = 0; j < 16; j++) {
        float e = __expf(l[j] - mx);
        se += e; pl += e * l[j];
    }
    float lse = mx + __logf(se);
    int a = action[row];
    float la = 0.f;
    #pragma unroll
    for (int j = 0; j < 16; j++) la = (a == j) ? l[j] : la;
    out[row * 3 + 0] = la - lse;
    out[row * 3 + 1] = lse - pl / se;
    out[row * 3 + 2] = v;
}

// ---------------------------------------------------------------------------
extern "C" void kernel_launch(void* const* d_in, const int* in_sizes, int n_in,
                              void* d_out, int out_size)
{
    const float* x    = (const float*)d_in[0];
    const float* done = (const float*)d_in[1];
    const int*   act  = (const int*)  d_in[2];
    const float* gru  = (const float*)d_in[3];
    const float* W1   = (const float*)d_in[4];
    const float* b1   = (const float*)d_in[5];
    const float* W2   = (const float*)d_in[6];
    const float* b2   = (const float*)d_in[7];
    const float* Wih  = (const float*)d_in[8];
    const float* bih  = (const float*)d_in[9];
    const float* Whh  = (const float*)d_in[10];
    const float* bhh  = (const float*)d_in[11];
    const float* Wa   = (const float*)d_in[12];
    const float* ba   = (const float*)d_in[13];
    const float* Wc   = (const float*)d_in[14];
    const float* bc   = (const float*)d_in[15];
    float* out = (float*)d_out;

    size_t enc_smem  = (size_t)(64 * EWs + 2 * 128 * EA) * sizeof(float);        // 102912 B
    size_t scan_smem = (size_t)(3 * 128 * WP + 2 * 128 * 12 + 128 * 25) * 4;     // 224768 B

    cudaFuncSetAttribute(encoder_kernel, cudaFuncAttributeMaxDynamicSharedMemorySize, (int)enc_smem);
    cudaFuncSetAttribute(scan_kernel,    cudaFuncAttributeMaxDynamicSharedMemorySize, (int)scan_smem);

    encoder_kernel<<<TBn / 64, 512, enc_smem>>>(x, W1, b1, W2, b2, Wih, bih);
    scan_kernel<<<128, 256, scan_smem>>>(done, gru, Whh, bhh, out);
    heads_kernel<<<TBn / 512, 512>>>(act, Wa, ba, Wc, bc, out);
}

// round 8
// speedup vs baseline: 1.1327x; 1.0022x over previous
#include <cuda_runtime.h>
#include <cstdint>

#define Tn  512
#define Bn  1024
#define Sn  64
#define An  16
#define Hn  128
#define TBn (Tn*Bn)

typedef unsigned long long ull;

__device__ float g_gx[(size_t)TBn * 384];      // gate preactivations [T*B, 3H]
__device__ float g_hidden[(size_t)TBn * Hn];   // hidden states [T*B, H]

// ---------------------------------------------------------------------------
// f32x2 + fast-math helpers
// ---------------------------------------------------------------------------
__device__ __forceinline__ ull pack2(float lo, float hi) {
    ull r;
    asm("mov.b64 %0, {%1, %2};" : "=l"(r)
        : "r"(__float_as_uint(lo)), "r"(__float_as_uint(hi)));
    return r;
}
__device__ __forceinline__ ull dup2(float v) { return pack2(v, v); }
__device__ __forceinline__ void unpack2(ull p, float& lo, float& hi) {
    unsigned int a, b;
    asm("mov.b64 {%0, %1}, %2;" : "=r"(a), "=r"(b) : "l"(p));
    lo = __uint_as_float(a); hi = __uint_as_float(b);
}
__device__ __forceinline__ void fma2(ull& d, ull a, ull b) {
    asm("fma.rn.f32x2 %0, %1, %2, %3;" : "=l"(d) : "l"(a), "l"(b), "l"(d));
}
__device__ __forceinline__ float tanh_fast(float x) {
    float y; asm("tanh.approx.f32 %0, %1;" : "=f"(y) : "f"(x)); return y;
}
__device__ __forceinline__ float sigmoid_fast(float x) {
    return fmaf(0.5f, tanh_fast(0.5f * x), 0.5f);
}

// ---------------------------------------------------------------------------
// Encoder (R3, best measured): fused x -> h1 -> h2 -> gx.
// 512 threads, 64 rows/block, 2 blocks/SM.
// rg = tid>>6 owns rows rg*8..+7 ; cg = tid&63 owns cols 2cg,2cg+1.
// aT[k][row] stride 68; Wt[k][col] stride 130, streamed in 64-k chunks.
// ---------------------------------------------------------------------------
#define EA  68
#define EWs 130

__device__ __forceinline__ void enc_gemm64(const float* __restrict__ ap,
                                           const float* __restrict__ wp,
                                           ull acc[4][2])
{
    #pragma unroll 4
    for (int k = 0; k < 64; k++) {
        ulonglong2 a01 = *(const ulonglong2*)(ap + k * EA);      // rows (0,1),(2,3)
        ulonglong2 a23 = *(const ulonglong2*)(ap + k * EA + 4);  // rows (4,5),(6,7)
        float2 wv = *(const float2*)(wp + k * EWs);
        ull w0 = dup2(wv.x), w1 = dup2(wv.y);
        fma2(acc[0][0], a01.x, w0); fma2(acc[1][0], a01.y, w0);
        fma2(acc[2][0], a23.x, w0); fma2(acc[3][0], a23.y, w0);
        fma2(acc[0][1], a01.x, w1); fma2(acc[1][1], a01.y, w1);
        fma2(acc[2][1], a23.x, w1); fma2(acc[3][1], a23.y, w1);
    }
}

__global__ void __launch_bounds__(512, 2) encoder_kernel(
    const float* __restrict__ x,
    const float* __restrict__ W1, const float* __restrict__ b1,
    const float* __restrict__ W2, const float* __restrict__ b2,
    const float* __restrict__ Wih, const float* __restrict__ bih)
{
    extern __shared__ float sm[];
    float* Wt  = sm;                    // 64*130  = 8320 floats
    float* h1T = sm + 64 * EWs;         // 128*68  = 8704 floats
    float* h2T = h1T + 128 * EA;        // 128*68
    float* xT  = h2T;                   // 64*68 aliased into h2T region

    int tid = threadIdx.x;
    int cg  = tid & 63;
    int rg  = tid >> 6;
    int base = blockIdx.x * 64;

    for (int idx = tid; idx < 64 * 64; idx += 512) {
        int k = idx & 63, r = idx >> 6;
        xT[k * EA + r] = x[(base + r) * 64 + k];
    }
    for (int idx = tid; idx < 64 * 128; idx += 512) {
        int k = idx & 63, j = idx >> 6;
        Wt[k * EWs + j] = W1[j * 64 + k];
    }
    __syncthreads();

    ull acc[4][2];

    // ---- Phase A: h1 = relu(x @ W1^T + b1) ----
    acc[0][0] = acc[1][0] = acc[2][0] = acc[3][0] = dup2(b1[2 * cg]);
    acc[0][1] = acc[1][1] = acc[2][1] = acc[3][1] = dup2(b1[2 * cg + 1]);
    enc_gemm64(xT + rg * 8, Wt + 2 * cg, acc);
    #pragma unroll
    for (int c01 = 0; c01 < 2; c01++) {
        float v[8];
        unpack2(acc[0][c01], v[0], v[1]); unpack2(acc[1][c01], v[2], v[3]);
        unpack2(acc[2][c01], v[4], v[5]); unpack2(acc[3][c01], v[6], v[7]);
        #pragma unroll
        for (int i = 0; i < 8; i++) v[i] = fmaxf(v[i], 0.f);
        int col = 2 * cg + c01;
        *(float4*)&h1T[col * EA + rg * 8]     = make_float4(v[0], v[1], v[2], v[3]);
        *(float4*)&h1T[col * EA + rg * 8 + 4] = make_float4(v[4], v[5], v[6], v[7]);
    }
    __syncthreads();

    // ---- Phase B: h2 = relu(h1 @ W2^T + b2), K=128 in 2 chunks ----
    acc[0][0] = acc[1][0] = acc[2][0] = acc[3][0] = dup2(b2[2 * cg]);
    acc[0][1] = acc[1][1] = acc[2][1] = acc[3][1] = dup2(b2[2 * cg + 1]);
    #pragma unroll 1
    for (int h = 0; h < 2; h++) {
        for (int idx = tid; idx < 64 * 128; idx += 512) {
            int kl = idx & 63, j = idx >> 6;
            Wt[kl * EWs + j] = W2[j * 128 + h * 64 + kl];
        }
        __syncthreads();
        enc_gemm64(h1T + (h * 64) * EA + rg * 8, Wt + 2 * cg, acc);
        __syncthreads();
    }
    #pragma unroll
    for (int c01 = 0; c01 < 2; c01++) {
        float v[8];
        unpack2(acc[0][c01], v[0], v[1]); unpack2(acc[1][c01], v[2], v[3]);
        unpack2(acc[2][c01], v[4], v[5]); unpack2(acc[3][c01], v[6], v[7]);
        #pragma unroll
        for (int i = 0; i < 8; i++) v[i] = fmaxf(v[i], 0.f);
        int col = 2 * cg + c01;
        *(float4*)&h2T[col * EA + rg * 8]     = make_float4(v[0], v[1], v[2], v[3]);
        *(float4*)&h2T[col * EA + rg * 8 + 4] = make_float4(v[4], v[5], v[6], v[7]);
    }
    __syncthreads();

    // ---- Phase C: gx = h2 @ Wih^T + bih : 3 col passes x 2 k-chunks ----
    #pragma unroll 1
    for (int pp = 0; pp < 3; pp++) {
        acc[0][0] = acc[1][0] = acc[2][0] = acc[3][0] = dup2(bih[pp * 128 + 2 * cg]);
        acc[0][1] = acc[1][1] = acc[2][1] = acc[3][1] = dup2(bih[pp * 128 + 2 * cg + 1]);
        #pragma unroll 1
        for (int h = 0; h < 2; h++) {
            for (int idx = tid; idx < 64 * 128; idx += 512) {
                int kl = idx & 63, j = idx >> 6;
                Wt[kl * EWs + j] = Wih[(pp * 128 + j) * 128 + h * 64 + kl];
            }
            __syncthreads();
            enc_gemm64(h2T + (h * 64) * EA + rg * 8, Wt + 2 * cg, acc);
            __syncthreads();
        }
        #pragma unroll
        for (int p = 0; p < 4; p++) {
            float v0a, v0b, v1a, v1b;
            unpack2(acc[p][0], v0a, v0b);
            unpack2(acc[p][1], v1a, v1b);
            size_t row0 = (size_t)(base + rg * 8 + 2 * p);
            *(float2*)&g_gx[row0 * 384 + pp * 128 + 2 * cg]       = make_float2(v0a, v1a);
            *(float2*)&g_gx[(row0 + 1) * 384 + pp * 128 + 2 * cg] = make_float2(v0b, v1b);
        }
    }
}

// ---------------------------------------------------------------------------
// GRU scan (R6): 128 blocks x 8 batch rows, 256 threads (c = col, kh = k-half).
// w planes [g][k][c] stride 130 (scalar LDS, conflict-free).
// hT[k][r] stride 12, double-buffered (LDS.128 broadcast, rows pre-paired).
// ---------------------------------------------------------------------------
#define WP 130

__global__ void __launch_bounds__(256, 1) scan_kernel(
    const float* __restrict__ done, const float* __restrict__ gru0,
    const float* __restrict__ Whh, const float* __restrict__ bhh,
    float* __restrict__ out)
{
    extern __shared__ float sm[];
    float* wsm = sm;                        // 3*128*130 = 49920 floats
    float* hb  = wsm + 3 * 128 * WP;        // 2*128*12  =  3072
    float* red = hb + 2 * 128 * 12;         // 128*25    =  3200

    int tid = threadIdx.x;
    int c   = tid & 127;
    int kh  = tid >> 7;
    int b0  = blockIdx.x << 3;

    for (int idx = tid; idx < 384 * 128; idx += 256) {
        int k = idx & 127, j = idx >> 7;
        int g = j >> 7, co = j & 127;
        wsm[g * 128 * WP + k * WP + co] = Whh[j * 128 + k];
    }
    for (int idx = tid; idx < 8 * 128; idx += 256) {
        int r = idx >> 7, f = idx & 127;
        hb[f * 12 + r] = gru0[(b0 + r) * 128 + f] * (1.f - done[b0 + r]);
    }
    __syncthreads();

    const float* w0 = wsm + c;
    const float* w1 = wsm + 128 * WP + c;
    const float* w2 = wsm + 256 * WP + c;

    float br = bhh[c], bz = bhh[c + 128], bn = bhh[c + 256];

    float gx0[8], gx1[8], gx2[8];
    if (kh == 0) {
        #pragma unroll
        for (int r = 0; r < 8; r++) {
            size_t row = (size_t)(b0 + r);
            gx0[r] = g_gx[row * 384 + c];
            gx1[r] = g_gx[row * 384 + 128 + c];
            gx2[r] = g_gx[row * 384 + 256 + c];
        }
    }

    int cur = 0;
    for (int t = 0; t < Tn; t++) {
        float gn0[8], gn1[8], gn2[8], dn[8];
        if (kh == 0) {
            int tnx = (t + 1 < Tn) ? (t + 1) : t;
            #pragma unroll
            for (int r = 0; r < 8; r++) {
                size_t row = (size_t)tnx * Bn + b0 + r;
                gn0[r] = g_gx[row * 384 + c];
                gn1[r] = g_gx[row * 384 + 128 + c];
                gn2[r] = g_gx[row * 384 + 256 + c];
                dn[r] = (t + 1 < Tn) ? done[(size_t)(t + 1) * Bn + b0 + r] : 0.f;
            }
        }

        const float* hbc = hb + cur * 1536;
        ull aR[4], aZ[4], aN[4];
        #pragma unroll
        for (int p = 0; p < 4; p++) { aR[p] = 0ull; aZ[p] = 0ull; aN[p] = 0ull; }

        const float* hk  = hbc + kh * 64 * 12;
        const float* wk0 = w0 + kh * 64 * WP;
        const float* wk1 = w1 + kh * 64 * WP;
        const float* wk2 = w2 + kh * 64 * WP;
        #pragma unroll 4
        for (int k = 0; k < 64; k++) {
            ulonglong2 h01 = *(const ulonglong2*)(hk + k * 12);      // rows 0-3
            ulonglong2 h23 = *(const ulonglong2*)(hk + k * 12 + 4);  // rows 4-7
            ull wr = dup2(wk0[k * WP]);
            ull wz = dup2(wk1[k * WP]);
            ull wn = dup2(wk2[k * WP]);
            fma2(aR[0], h01.x, wr); fma2(aR[1], h01.y, wr);
            fma2(aR[2], h23.x, wr); fma2(aR[3], h23.y, wr);
            fma2(aZ[0], h01.x, wz); fma2(aZ[1], h01.y, wz);
            fma2(aZ[2], h23.x, wz); fma2(aZ[3], h23.y, wz);
            fma2(aN[0], h01.x, wn); fma2(aN[1], h01.y, wn);
            fma2(aN[2], h23.x, wn); fma2(aN[3], h23.y, wn);
        }

        float pr[8], pz[8], pn[8];
        #pragma unroll
        for (int p = 0; p < 4; p++) {
            unpack2(aR[p], pr[2 * p], pr[2 * p + 1]);
            unpack2(aZ[p], pz[2 * p], pz[2 * p + 1]);
            unpack2(aN[p], pn[2 * p], pn[2 * p + 1]);
        }

        if (kh == 1) {
            #pragma unroll
            for (int r = 0; r < 8; r++) {
                red[c * 25 + r]      = pr[r];
                red[c * 25 + 8 + r]  = pz[r];
                red[c * 25 + 16 + r] = pn[r];
            }
        }
        __syncthreads();

        if (kh == 0) {
            float ho[8];
            ulonglong2 h01 = *(const ulonglong2*)(hbc + c * 12);
            ulonglong2 h23 = *(const ulonglong2*)(hbc + c * 12 + 4);
            unpack2(h01.x, ho[0], ho[1]); unpack2(h01.y, ho[2], ho[3]);
            unpack2(h23.x, ho[4], ho[5]); unpack2(h23.y, ho[6], ho[7]);

            float* hnxt = hb + (cur ^ 1) * 1536;
            float hnv[8];
            #pragma unroll
            for (int r = 0; r < 8; r++) {
                float sr = pr[r] + red[c * 25 + r]      + br + gx0[r];
                float sz = pz[r] + red[c * 25 + 8 + r]  + bz + gx1[r];
                float sn = pn[r] + red[c * 25 + 16 + r] + bn;
                float rg = sigmoid_fast(sr);
                float zg = sigmoid_fast(sz);
                float ng = tanh_fast(gx2[r] + rg * sn);
                float hnew = (1.f - zg) * ng + zg * ho[r];
                hnv[r] = hnew;
                g_hidden[((size_t)t * Bn + b0 + r) * Hn + c] = hnew;
                gx0[r] = gn0[r]; gx1[r] = gn1[r]; gx2[r] = gn2[r];
            }
            *(float4*)&hnxt[c * 12] = make_float4(
                hnv[0] * (1.f - dn[0]), hnv[1] * (1.f - dn[1]),
                hnv[2] * (1.f - dn[2]), hnv[3] * (1.f - dn[3]));
            *(float4*)&hnxt[c * 12 + 4] = make_float4(
                hnv[4] * (1.f - dn[4]), hnv[5] * (1.f - dn[5]),
                hnv[6] * (1.f - dn[6]), hnv[7] * (1.f - dn[7]));
            if (t == Tn - 1) {
                #pragma unroll
                for (int r = 0; r < 8; r++)
                    out[(size_t)TBn * 3 + (b0 + r) * Hn + c] = hnv[r];
            }
        }
        __syncthreads();
        cur ^= 1;
    }
}

// ---------------------------------------------------------------------------
// Heads (new): thread-per-row, h read directly from global (LDG.128 stream),
// only Wa/Wc/biases in static smem (8.7 KB) -> high occupancy, DRAM-bound.
// ---------------------------------------------------------------------------
__global__ void __launch_bounds__(512, 4) heads_kernel(
    const int* __restrict__ action,
    const float* __restrict__ Wa, const float* __restrict__ ba,
    const float* __restrict__ Wc, const float* __restrict__ bc,
    float* __restrict__ out)
{
    __shared__ float swa[16 * 128];
    __shared__ float swc[128];
    __shared__ float sba[16];
    __shared__ float sbc;

    int tid = threadIdx.x;
    for (int i = tid; i < 16 * 128; i += 512) swa[i] = Wa[i];
    if (tid < 128) swc[tid] = Wc[tid];
    if (tid < 16)  sba[tid] = ba[tid];
    if (tid == 0)  sbc = bc[0];
    __syncthreads();

    size_t row = (size_t)blockIdx.x * 512 + tid;
    const float* hrow = &g_hidden[row * 128];

    float l[16];
    #pragma unroll
    for (int j = 0; j < 16; j++) l[j] = sba[j];
    float v = sbc;

    #pragma unroll 4
    for (int k4 = 0; k4 < 32; k4++) {
        float4 h4 = *(const float4*)(hrow + k4 * 4);
        const float* wa = &swa[k4 * 4];
        #pragma unroll
        for (int j = 0; j < 16; j++) {
            l[j] += wa[j * 128]     * h4.x;
            l[j] += wa[j * 128 + 1] * h4.y;
            l[j] += wa[j * 128 + 2] * h4.z;
            l[j] += wa[j * 128 + 3] * h4.w;
        }
        v += swc[k4 * 4]     * h4.x + swc[k4 * 4 + 1] * h4.y
           + swc[k4 * 4 + 2] * h4.z + swc[k4 * 4 + 3] * h4.w;
    }

    float mx = l[0];
    #pragma unroll
    for (int j = 1; j < 16; j++) mx = fmaxf(mx, l[j]);
    float se = 0.f, pl = 0.f;
    #pragma unroll
    for (int j = 0; j < 16; j++) {
        float e = __expf(l[j] - mx);
        se += e; pl += e * l[j];
    }
    float lse = mx + __logf(se);
    int a = action[row];
    float la = 0.f;
    #pragma unroll
    for (int j = 0; j < 16; j++) la = (a == j) ? l[j] : la;
    out[row * 3 + 0] = la - lse;
    out[row * 3 + 1] = lse - pl / se;
    out[row * 3 + 2] = v;
}

// ---------------------------------------------------------------------------
extern "C" void kernel_launch(void* const* d_in, const int* in_sizes, int n_in,
                              void* d_out, int out_size)
{
    const float* x    = (const float*)d_in[0];
    const float* done = (const float*)d_in[1];
    const int*   act  = (const int*)  d_in[2];
    const float* gru  = (const float*)d_in[3];
    const float* W1   = (const float*)d_in[4];
    const float* b1   = (const float*)d_in[5];
    const float* W2   = (const float*)d_in[6];
    const float* b2   = (const float*)d_in[7];
    const float* Wih  = (const float*)d_in[8];
    const float* bih  = (const float*)d_in[9];
    const float* Whh  = (const float*)d_in[10];
    const float* bhh  = (const float*)d_in[11];
    const float* Wa   = (const float*)d_in[12];
    const float* ba   = (const float*)d_in[13];
    const float* Wc   = (const float*)d_in[14];
    const float* bc   = (const float*)d_in[15];
    float* out = (float*)d_out;

    size_t enc_smem  = (size_t)(64 * EWs + 2 * 128 * EA) * sizeof(float);        // 102912 B
    size_t scan_smem = (size_t)(3 * 128 * WP + 2 * 128 * 12 + 128 * 25) * 4;     // 224768 B

    cudaFuncSetAttribute(encoder_kernel, cudaFuncAttributeMaxDynamicSharedMemorySize, (int)enc_smem);
    cudaFuncSetAttribute(scan_kernel,    cudaFuncAttributeMaxDynamicSharedMemorySize, (int)scan_smem);

    encoder_kernel<<<TBn / 64, 512, enc_smem>>>(x, W1, b1, W2, b2, Wih, bih);
    scan_kernel<<<128, 256, scan_smem>>>(done, gru, Whh, bhh, out);
    heads_kernel<<<TBn / 512, 512>>>(act, Wa, ba, Wc, bc, out);
}

// round 9
// speedup vs baseline: 1.1696x; 1.0326x over previous
#include <cuda_runtime.h>
#include <cstdint>

#define Tn  512
#define Bn  1024
#define Sn  64
#define An  16
#define Hn  128
#define TBn (Tn*Bn)

typedef unsigned long long ull;

__device__ float g_gx[(size_t)TBn * 384];      // gate preactivations [T*B, 3H]
__device__ float g_hidden[(size_t)TBn * Hn];   // hidden states [T*B, H]

// ---------------------------------------------------------------------------
// f32x2 + fast-math helpers
// ---------------------------------------------------------------------------
__device__ __forceinline__ ull pack2(float lo, float hi) {
    ull r;
    asm("mov.b64 %0, {%1, %2};" : "=l"(r)
        : "r"(__float_as_uint(lo)), "r"(__float_as_uint(hi)));
    return r;
}
__device__ __forceinline__ ull dup2(float v) { return pack2(v, v); }
__device__ __forceinline__ void unpack2(ull p, float& lo, float& hi) {
    unsigned int a, b;
    asm("mov.b64 {%0, %1}, %2;" : "=r"(a), "=r"(b) : "l"(p));
    lo = __uint_as_float(a); hi = __uint_as_float(b);
}
__device__ __forceinline__ void fma2(ull& d, ull a, ull b) {
    asm("fma.rn.f32x2 %0, %1, %2, %3;" : "=l"(d) : "l"(a), "l"(b), "l"(d));
}
__device__ __forceinline__ float tanh_fast(float x) {
    float y; asm("tanh.approx.f32 %0, %1;" : "=f"(y) : "f"(x)); return y;
}
__device__ __forceinline__ float sigmoid_fast(float x) {
    return fmaf(0.5f, tanh_fast(0.5f * x), 0.5f);
}

// ---------------------------------------------------------------------------
// Encoder: fused x -> h1 -> h2 -> gx.  512 threads, 128 rows/block, 2 blk/SM.
// rg = tid>>5 owns rows rg*8..+7 ; cg = tid&31 owns cols 4cg..4cg+3.
// ONE activation buffer ABUF[k][row] stride 132, overwritten in place
// (x -> h1 -> h2); W chunk Wt[k][col] stride 132, streamed per 64 k.
// Per warp-k: 2 broadcast LDS.128 (a) + 1 LDS.128 (w float4) + 16 FFMA2.
// ---------------------------------------------------------------------------
#define SA 132

__device__ __forceinline__ void enc_gemm64(const float* __restrict__ ap,
                                           const float* __restrict__ wp,
                                           ull acc[4][4])
{
    #pragma unroll 2
    for (int k = 0; k < 64; k++) {
        ulonglong2 aA = *(const ulonglong2*)(ap + k * SA);      // rows (0,1),(2,3)
        ulonglong2 aB = *(const ulonglong2*)(ap + k * SA + 4);  // rows (4,5),(6,7)
        float4 wv = *(const float4*)(wp + k * SA);
        ull w0 = dup2(wv.x), w1 = dup2(wv.y), w2 = dup2(wv.z), w3 = dup2(wv.w);
        fma2(acc[0][0], aA.x, w0); fma2(acc[1][0], aA.y, w0);
        fma2(acc[2][0], aB.x, w0); fma2(acc[3][0], aB.y, w0);
        fma2(acc[0][1], aA.x, w1); fma2(acc[1][1], aA.y, w1);
        fma2(acc[2][1], aB.x, w1); fma2(acc[3][1], aB.y, w1);
        fma2(acc[0][2], aA.x, w2); fma2(acc[1][2], aA.y, w2);
        fma2(acc[2][2], aB.x, w2); fma2(acc[3][2], aB.y, w2);
        fma2(acc[0][3], aA.x, w3); fma2(acc[1][3], aA.y, w3);
        fma2(acc[2][3], aB.x, w3); fma2(acc[3][3], aB.y, w3);
    }
}

__global__ void __launch_bounds__(512, 2) encoder_kernel(
    const float* __restrict__ x,
    const float* __restrict__ W1, const float* __restrict__ b1,
    const float* __restrict__ W2, const float* __restrict__ b2,
    const float* __restrict__ Wih, const float* __restrict__ bih)
{
    extern __shared__ float sm[];
    float* Wt   = sm;                   // 64*132  = 8448 floats (33792 B)
    float* ABUF = sm + 64 * SA;         // 128*132 = 16896 floats (67584 B)

    int tid = threadIdx.x;
    int cg  = tid & 31;
    int rg  = tid >> 5;
    size_t base = (size_t)blockIdx.x * 128;

    // stage xT (128 rows x 64 k, transposed) + W1 (K=64, one chunk)
    for (int idx = tid; idx < 128 * 64; idx += 512) {
        int r = idx >> 6, k = idx & 63;
        ABUF[k * SA + r] = x[(base + r) * 64 + k];
    }
    for (int idx = tid; idx < 64 * 128; idx += 512) {
        int k = idx & 63, j = idx >> 6;
        Wt[k * SA + j] = W1[j * 64 + k];
    }
    __syncthreads();

    ull acc[4][4];

    // ---- Phase A: h1 = relu(x @ W1^T + b1), K=64 ----
    #pragma unroll
    for (int c = 0; c < 4; c++) {
        ull bb = dup2(b1[4 * cg + c]);
        acc[0][c] = bb; acc[1][c] = bb; acc[2][c] = bb; acc[3][c] = bb;
    }
    enc_gemm64(ABUF + rg * 8, Wt + 4 * cg, acc);
    __syncthreads();   // all ABUF/Wt reads done before overwrite
    #pragma unroll
    for (int c = 0; c < 4; c++) {
        int col = 4 * cg + c;
        float v[8];
        unpack2(acc[0][c], v[0], v[1]); unpack2(acc[1][c], v[2], v[3]);
        unpack2(acc[2][c], v[4], v[5]); unpack2(acc[3][c], v[6], v[7]);
        #pragma unroll
        for (int i = 0; i < 8; i++) v[i] = fmaxf(v[i], 0.f);
        *(float4*)&ABUF[col * SA + rg * 8]     = make_float4(v[0], v[1], v[2], v[3]);
        *(float4*)&ABUF[col * SA + rg * 8 + 4] = make_float4(v[4], v[5], v[6], v[7]);
    }
    __syncthreads();

    // ---- Phase B: h2 = relu(h1 @ W2^T + b2), K=128 in 2 chunks ----
    #pragma unroll
    for (int c = 0; c < 4; c++) {
        ull bb = dup2(b2[4 * cg + c]);
        acc[0][c] = bb; acc[1][c] = bb; acc[2][c] = bb; acc[3][c] = bb;
    }
    #pragma unroll 1
    for (int h = 0; h < 2; h++) {
        for (int idx = tid; idx < 64 * 128; idx += 512) {
            int kl = idx & 63, j = idx >> 6;
            Wt[kl * SA + j] = W2[j * 128 + h * 64 + kl];
        }
        __syncthreads();
        enc_gemm64(ABUF + (h * 64) * SA + rg * 8, Wt + 4 * cg, acc);
        __syncthreads();   // gemm reads done (ABUF safe to overwrite / Wt to restage)
    }
    #pragma unroll
    for (int c = 0; c < 4; c++) {
        int col = 4 * cg + c;
        float v[8];
        unpack2(acc[0][c], v[0], v[1]); unpack2(acc[1][c], v[2], v[3]);
        unpack2(acc[2][c], v[4], v[5]); unpack2(acc[3][c], v[6], v[7]);
        #pragma unroll
        for (int i = 0; i < 8; i++) v[i] = fmaxf(v[i], 0.f);
        *(float4*)&ABUF[col * SA + rg * 8]     = make_float4(v[0], v[1], v[2], v[3]);
        *(float4*)&ABUF[col * SA + rg * 8 + 4] = make_float4(v[4], v[5], v[6], v[7]);
    }
    __syncthreads();

    // ---- Phase C: gx = h2 @ Wih^T + bih, 3 col passes x 2 k chunks ----
    #pragma unroll 1
    for (int pp = 0; pp < 3; pp++) {
        #pragma unroll
        for (int c = 0; c < 4; c++) {
            ull bb = dup2(bih[pp * 128 + 4 * cg + c]);
            acc[0][c] = bb; acc[1][c] = bb; acc[2][c] = bb; acc[3][c] = bb;
        }
        #pragma unroll 1
        for (int h = 0; h < 2; h++) {
            for (int idx = tid; idx < 64 * 128; idx += 512) {
                int kl = idx & 63, j = idx >> 6;
                Wt[kl * SA + j] = Wih[(pp * 128 + j) * 128 + h * 64 + kl];
            }
            __syncthreads();
            enc_gemm64(ABUF + (h * 64) * SA + rg * 8, Wt + 4 * cg, acc);
            __syncthreads();
        }
        // store: float4 per row (cols 4cg..4cg+3 contiguous)
        #pragma unroll
        for (int p = 0; p < 4; p++) {
            float va[4], vb[4];
            #pragma unroll
            for (int c = 0; c < 4; c++) unpack2(acc[p][c], va[c], vb[c]);
            size_t row0 = base + rg * 8 + 2 * p;
            *(float4*)&g_gx[row0 * 384 + pp * 128 + 4 * cg] =
                make_float4(va[0], va[1], va[2], va[3]);
            *(float4*)&g_gx[(row0 + 1) * 384 + pp * 128 + 4 * cg] =
                make_float4(vb[0], vb[1], vb[2], vb[3]);
        }
    }
}

// ---------------------------------------------------------------------------
// GRU scan (measured-best): 128 blocks x 8 rows, 256 threads (c = col, kh = k-half).
// w planes [g][k][c] stride 130 (conflict-free scalar LDS);
// hT[k][r] stride 12, double-buffered.
// ---------------------------------------------------------------------------
#define WP 130

__global__ void __launch_bounds__(256, 1) scan_kernel(
    const float* __restrict__ done, const float* __restrict__ gru0,
    const float* __restrict__ Whh, const float* __restrict__ bhh,
    float* __restrict__ out)
{
    extern __shared__ float sm[];
    float* wsm = sm;                        // 3*128*130 = 49920 floats
    float* hb  = wsm + 3 * 128 * WP;        // 2*128*12  =  3072
    float* red = hb + 2 * 128 * 12;         // 128*25    =  3200

    int tid = threadIdx.x;
    int c   = tid & 127;
    int kh  = tid >> 7;
    int b0  = blockIdx.x << 3;

    for (int idx = tid; idx < 384 * 128; idx += 256) {
        int k = idx & 127, j = idx >> 7;
        int g = j >> 7, co = j & 127;
        wsm[g * 128 * WP + k * WP + co] = Whh[j * 128 + k];
    }
    for (int idx = tid; idx < 8 * 128; idx += 256) {
        int r = idx >> 7, f = idx & 127;
        hb[f * 12 + r] = gru0[(b0 + r) * 128 + f] * (1.f - done[b0 + r]);
    }
    __syncthreads();

    const float* w0 = wsm + c;
    const float* w1 = wsm + 128 * WP + c;
    const float* w2 = wsm + 256 * WP + c;

    float br = bhh[c], bz = bhh[c + 128], bn = bhh[c + 256];

    float gx0[8], gx1[8], gx2[8];
    if (kh == 0) {
        #pragma unroll
        for (int r = 0; r < 8; r++) {
            size_t row = (size_t)(b0 + r);
            gx0[r] = g_gx[row * 384 + c];
            gx1[r] = g_gx[row * 384 + 128 + c];
            gx2[r] = g_gx[row * 384 + 256 + c];
        }
    }

    int cur = 0;
    for (int t = 0; t < Tn; t++) {
        float gn0[8], gn1[8], gn2[8], dn[8];
        if (kh == 0) {
            int tnx = (t + 1 < Tn) ? (t + 1) : t;
            #pragma unroll
            for (int r = 0; r < 8; r++) {
                size_t row = (size_t)tnx * Bn + b0 + r;
                gn0[r] = g_gx[row * 384 + c];
                gn1[r] = g_gx[row * 384 + 128 + c];
                gn2[r] = g_gx[row * 384 + 256 + c];
                dn[r] = (t + 1 < Tn) ? done[(size_t)(t + 1) * Bn + b0 + r] : 0.f;
            }
        }

        const float* hbc = hb + cur * 1536;
        ull aR[4], aZ[4], aN[4];
        #pragma unroll
        for (int p = 0; p < 4; p++) { aR[p] = 0ull; aZ[p] = 0ull; aN[p] = 0ull; }

        const float* hk  = hbc + kh * 64 * 12;
        const float* wk0 = w0 + kh * 64 * WP;
        const float* wk1 = w1 + kh * 64 * WP;
        const float* wk2 = w2 + kh * 64 * WP;
        #pragma unroll 4
        for (int k = 0; k < 64; k++) {
            ulonglong2 h01 = *(const ulonglong2*)(hk + k * 12);      // rows 0-3
            ulonglong2 h23 = *(const ulonglong2*)(hk + k * 12 + 4);  // rows 4-7
            ull wr = dup2(wk0[k * WP]);
            ull wz = dup2(wk1[k * WP]);
            ull wn = dup2(wk2[k * WP]);
            fma2(aR[0], h01.x, wr); fma2(aR[1], h01.y, wr);
            fma2(aR[2], h23.x, wr); fma2(aR[3], h23.y, wr);
            fma2(aZ[0], h01.x, wz); fma2(aZ[1], h01.y, wz);
            fma2(aZ[2], h23.x, wz); fma2(aZ[3], h23.y, wz);
            fma2(aN[0], h01.x, wn); fma2(aN[1], h01.y, wn);
            fma2(aN[2], h23.x, wn); fma2(aN[3], h23.y, wn);
        }

        float pr[8], pz[8], pn[8];
        #pragma unroll
        for (int p = 0; p < 4; p++) {
            unpack2(aR[p], pr[2 * p], pr[2 * p + 1]);
            unpack2(aZ[p], pz[2 * p], pz[2 * p + 1]);
            unpack2(aN[p], pn[2 * p], pn[2 * p + 1]);
        }

        if (kh == 1) {
            #pragma unroll
            for (int r = 0; r < 8; r++) {
                red[c * 25 + r]      = pr[r];
                red[c * 25 + 8 + r]  = pz[r];
                red[c * 25 + 16 + r] = pn[r];
            }
        }
        __syncthreads();

        if (kh == 0) {
            float ho[8];
            ulonglong2 h01 = *(const ulonglong2*)(hbc + c * 12);
            ulonglong2 h23 = *(const ulonglong2*)(hbc + c * 12 + 4);
            unpack2(h01.x, ho[0], ho[1]); unpack2(h01.y, ho[2], ho[3]);
            unpack2(h23.x, ho[4], ho[5]); unpack2(h23.y, ho[6], ho[7]);

            float* hnxt = hb + (cur ^ 1) * 1536;
            float hnv[8];
            #pragma unroll
            for (int r = 0; r < 8; r++) {
                float sr = pr[r] + red[c * 25 + r]      + br + gx0[r];
                float sz = pz[r] + red[c * 25 + 8 + r]  + bz + gx1[r];
                float sn = pn[r] + red[c * 25 + 16 + r] + bn;
                float rg = sigmoid_fast(sr);
                float zg = sigmoid_fast(sz);
                float ng = tanh_fast(gx2[r] + rg * sn);
                float hnew = (1.f - zg) * ng + zg * ho[r];
                hnv[r] = hnew;
                g_hidden[((size_t)t * Bn + b0 + r) * Hn + c] = hnew;
                gx0[r] = gn0[r]; gx1[r] = gn1[r]; gx2[r] = gn2[r];
            }
            *(float4*)&hnxt[c * 12] = make_float4(
                hnv[0] * (1.f - dn[0]), hnv[1] * (1.f - dn[1]),
                hnv[2] * (1.f - dn[2]), hnv[3] * (1.f - dn[3]));
            *(float4*)&hnxt[c * 12 + 4] = make_float4(
                hnv[4] * (1.f - dn[4]), hnv[5] * (1.f - dn[5]),
                hnv[6] * (1.f - dn[6]), hnv[7] * (1.f - dn[7]));
            if (t == Tn - 1) {
                #pragma unroll
                for (int r = 0; r < 8; r++)
                    out[(size_t)TBn * 3 + (b0 + r) * Hn + c] = hnv[r];
            }
        }
        __syncthreads();
        cur ^= 1;
    }
}

// ---------------------------------------------------------------------------
// Heads (measured-best): thread-per-row, h streamed from global (LDG.128),
// Wa/Wc/biases in 8.7 KB static smem.
// ---------------------------------------------------------------------------
__global__ void __launch_bounds__(512, 4) heads_kernel(
    const int* __restrict__ action,
    const float* __restrict__ Wa, const float* __restrict__ ba,
    const float* __restrict__ Wc, const float* __restrict__ bc,
    float* __restrict__ out)
{
    __shared__ float swa[16 * 128];
    __shared__ float swc[128];
    __shared__ float sba[16];
    __shared__ float sbc;

    int tid = threadIdx.x;
    for (int i = tid; i < 16 * 128; i += 512) swa[i] = Wa[i];
    if (tid < 128) swc[tid] = Wc[tid];
    if (tid < 16)  sba[tid] = ba[tid];
    if (tid == 0)  sbc = bc[0];
    __syncthreads();

    size_t row = (size_t)blockIdx.x * 512 + tid;
    const float* hrow = &g_hidden[row * 128];

    float l[16];
    #pragma unroll
    for (int j = 0; j < 16; j++) l[j] = sba[j];
    float v = sbc;

    #pragma unroll 4
    for (int k4 = 0; k4 < 32; k4++) {
        float4 h4 = *(const float4*)(hrow + k4 * 4);
        const float* wa = &swa[k4 * 4];
        #pragma unroll
        for (int j = 0; j < 16; j++) {
            l[j] += wa[j * 128]     * h4.x;
            l[j] += wa[j * 128 + 1] * h4.y;
            l[j] += wa[j * 128 + 2] * h4.z;
            l[j] += wa[j * 128 + 3] * h4.w;
        }
        v += swc[k4 * 4]     * h4.x + swc[k4 * 4 + 1] * h4.y
           + swc[k4 * 4 + 2] * h4.z + swc[k4 * 4 + 3] * h4.w;
    }

    float mx = l[0];
    #pragma unroll
    for (int j = 1; j < 16; j++) mx = fmaxf(mx, l[j]);
    float se = 0.f, pl = 0.f;
    #pragma unroll
    for (int j = 0; j < 16; j++) {
        float e = __expf(l[j] - mx);
        se += e; pl += e * l[j];
    }
    float lse = mx + __logf(se);
    int a = action[row];
    float la = 0.f;
    #pragma unroll
    for (int j = 0; j < 16; j++) la = (a == j) ? l[j] : la;
    out[row * 3 + 0] = la - lse;
    out[row * 3 + 1] = lse - pl / se;
    out[row * 3 + 2] = v;
}

// ---------------------------------------------------------------------------
extern "C" void kernel_launch(void* const* d_in, const int* in_sizes, int n_in,
                              void* d_out, int out_size)
{
    const float* x    = (const float*)d_in[0];
    const float* done = (const float*)d_in[1];
    const int*   act  = (const int*)  d_in[2];
    const float* gru  = (const float*)d_in[3];
    const float* W1   = (const float*)d_in[4];
    const float* b1   = (const float*)d_in[5];
    const float* W2   = (const float*)d_in[6];
    const float* b2   = (const float*)d_in[7];
    const float* Wih  = (const float*)d_in[8];
    const float* bih  = (const float*)d_in[9];
    const float* Whh  = (const float*)d_in[10];
    const float* bhh  = (const float*)d_in[11];
    const float* Wa   = (const float*)d_in[12];
    const float* ba   = (const float*)d_in[13];
    const float* Wc   = (const float*)d_in[14];
    const float* bc   = (const float*)d_in[15];
    float* out = (float*)d_out;

    size_t enc_smem  = (size_t)(64 * SA + 128 * SA) * sizeof(float);             // 101376 B
    size_t scan_smem = (size_t)(3 * 128 * WP + 2 * 128 * 12 + 128 * 25) * 4;     // 224768 B

    cudaFuncSetAttribute(encoder_kernel, cudaFuncAttributeMaxDynamicSharedMemorySize, (int)enc_smem);
    cudaFuncSetAttribute(scan_kernel,    cudaFuncAttributeMaxDynamicSharedMemorySize, (int)scan_smem);

    encoder_kernel<<<TBn / 128, 512, enc_smem>>>(x, W1, b1, W2, b2, Wih, bih);
    scan_kernel<<<128, 256, scan_smem>>>(done, gru, Whh, bhh, out);
    heads_kernel<<<TBn / 512, 512>>>(act, Wa, ba, Wc, bc, out);
}

// round 10
// speedup vs baseline: 1.1828x; 1.0113x over previous
#include <cuda_runtime.h>
#include <cstdint>

#define Tn  512
#define Bn  1024
#define Sn  64
#define An  16
#define Hn  128
#define TBn (Tn*Bn)

typedef unsigned long long ull;

__device__ float g_gx[(size_t)TBn * 384];      // gate preactivations [T*B, 3H]
__device__ float g_hidden[(size_t)TBn * Hn];   // hidden states [T*B, H]

// ---------------------------------------------------------------------------
// f32x2 + fast-math helpers
// ---------------------------------------------------------------------------
__device__ __forceinline__ ull pack2(float lo, float hi) {
    ull r;
    asm("mov.b64 %0, {%1, %2};" : "=l"(r)
        : "r"(__float_as_uint(lo)), "r"(__float_as_uint(hi)));
    return r;
}
__device__ __forceinline__ ull dup2(float v) { return pack2(v, v); }
__device__ __forceinline__ void unpack2(ull p, float& lo, float& hi) {
    unsigned int a, b;
    asm("mov.b64 {%0, %1}, %2;" : "=r"(a), "=r"(b) : "l"(p));
    lo = __uint_as_float(a); hi = __uint_as_float(b);
}
__device__ __forceinline__ void fma2(ull& d, ull a, ull b) {
    asm("fma.rn.f32x2 %0, %1, %2, %3;" : "=l"(d) : "l"(a), "l"(b), "l"(d));
}
__device__ __forceinline__ ull add2(ull a, ull b) {
    ull d;
    asm("add.rn.f32x2 %0, %1, %2;" : "=l"(d) : "l"(a), "l"(b));
    return d;
}
__device__ __forceinline__ float tanh_fast(float x) {
    float y; asm("tanh.approx.f32 %0, %1;" : "=f"(y) : "f"(x)); return y;
}
__device__ __forceinline__ float sigmoid_fast(float x) {
    return fmaf(0.5f, tanh_fast(0.5f * x), 0.5f);
}

// ---------------------------------------------------------------------------
// Encoder (R9 measured-best): fused x -> h1 -> h2 -> gx.
// 512 threads, 128 rows/block, 2 blk/SM; 8x4 microtile; in-place ABUF.
// ---------------------------------------------------------------------------
#define SA 132

__device__ __forceinline__ void enc_gemm64(const float* __restrict__ ap,
                                           const float* __restrict__ wp,
                                           ull acc[4][4])
{
    #pragma unroll 2
    for (int k = 0; k < 64; k++) {
        ulonglong2 aA = *(const ulonglong2*)(ap + k * SA);
        ulonglong2 aB = *(const ulonglong2*)(ap + k * SA + 4);
        float4 wv = *(const float4*)(wp + k * SA);
        ull w0 = dup2(wv.x), w1 = dup2(wv.y), w2 = dup2(wv.z), w3 = dup2(wv.w);
        fma2(acc[0][0], aA.x, w0); fma2(acc[1][0], aA.y, w0);
        fma2(acc[2][0], aB.x, w0); fma2(acc[3][0], aB.y, w0);
        fma2(acc[0][1], aA.x, w1); fma2(acc[1][1], aA.y, w1);
        fma2(acc[2][1], aB.x, w1); fma2(acc[3][1], aB.y, w1);
        fma2(acc[0][2], aA.x, w2); fma2(acc[1][2], aA.y, w2);
        fma2(acc[2][2], aB.x, w2); fma2(acc[3][2], aB.y, w2);
        fma2(acc[0][3], aA.x, w3); fma2(acc[1][3], aA.y, w3);
        fma2(acc[2][3], aB.x, w3); fma2(acc[3][3], aB.y, w3);
    }
}

__global__ void __launch_bounds__(512, 2) encoder_kernel(
    const float* __restrict__ x,
    const float* __restrict__ W1, const float* __restrict__ b1,
    const float* __restrict__ W2, const float* __restrict__ b2,
    const float* __restrict__ Wih, const float* __restrict__ bih)
{
    extern __shared__ float sm[];
    float* Wt   = sm;                   // 64*132 floats
    float* ABUF = sm + 64 * SA;         // 128*132 floats

    int tid = threadIdx.x;
    int cg  = tid & 31;
    int rg  = tid >> 5;
    size_t base = (size_t)blockIdx.x * 128;

    for (int idx = tid; idx < 128 * 64; idx += 512) {
        int r = idx >> 6, k = idx & 63;
        ABUF[k * SA + r] = x[(base + r) * 64 + k];
    }
    for (int idx = tid; idx < 64 * 128; idx += 512) {
        int k = idx & 63, j = idx >> 6;
        Wt[k * SA + j] = W1[j * 64 + k];
    }
    __syncthreads();

    ull acc[4][4];

    // Phase A
    #pragma unroll
    for (int c = 0; c < 4; c++) {
        ull bb = dup2(b1[4 * cg + c]);
        acc[0][c] = bb; acc[1][c] = bb; acc[2][c] = bb; acc[3][c] = bb;
    }
    enc_gemm64(ABUF + rg * 8, Wt + 4 * cg, acc);
    __syncthreads();
    #pragma unroll
    for (int c = 0; c < 4; c++) {
        int col = 4 * cg + c;
        float v[8];
        unpack2(acc[0][c], v[0], v[1]); unpack2(acc[1][c], v[2], v[3]);
        unpack2(acc[2][c], v[4], v[5]); unpack2(acc[3][c], v[6], v[7]);
        #pragma unroll
        for (int i = 0; i < 8; i++) v[i] = fmaxf(v[i], 0.f);
        *(float4*)&ABUF[col * SA + rg * 8]     = make_float4(v[0], v[1], v[2], v[3]);
        *(float4*)&ABUF[col * SA + rg * 8 + 4] = make_float4(v[4], v[5], v[6], v[7]);
    }
    __syncthreads();

    // Phase B
    #pragma unroll
    for (int c = 0; c < 4; c++) {
        ull bb = dup2(b2[4 * cg + c]);
        acc[0][c] = bb; acc[1][c] = bb; acc[2][c] = bb; acc[3][c] = bb;
    }
    #pragma unroll 1
    for (int h = 0; h < 2; h++) {
        for (int idx = tid; idx < 64 * 128; idx += 512) {
            int kl = idx & 63, j = idx >> 6;
            Wt[kl * SA + j] = W2[j * 128 + h * 64 + kl];
        }
        __syncthreads();
        enc_gemm64(ABUF + (h * 64) * SA + rg * 8, Wt + 4 * cg, acc);
        __syncthreads();
    }
    #pragma unroll
    for (int c = 0; c < 4; c++) {
        int col = 4 * cg + c;
        float v[8];
        unpack2(acc[0][c], v[0], v[1]); unpack2(acc[1][c], v[2], v[3]);
        unpack2(acc[2][c], v[4], v[5]); unpack2(acc[3][c], v[6], v[7]);
        #pragma unroll
        for (int i = 0; i < 8; i++) v[i] = fmaxf(v[i], 0.f);
        *(float4*)&ABUF[col * SA + rg * 8]     = make_float4(v[0], v[1], v[2], v[3]);
        *(float4*)&ABUF[col * SA + rg * 8 + 4] = make_float4(v[4], v[5], v[6], v[7]);
    }
    __syncthreads();

    // Phase C
    #pragma unroll 1
    for (int pp = 0; pp < 3; pp++) {
        #pragma unroll
        for (int c = 0; c < 4; c++) {
            ull bb = dup2(bih[pp * 128 + 4 * cg + c]);
            acc[0][c] = bb; acc[1][c] = bb; acc[2][c] = bb; acc[3][c] = bb;
        }
        #pragma unroll 1
        for (int h = 0; h < 2; h++) {
            for (int idx = tid; idx < 64 * 128; idx += 512) {
                int kl = idx & 63, j = idx >> 6;
                Wt[kl * SA + j] = Wih[(pp * 128 + j) * 128 + h * 64 + kl];
            }
            __syncthreads();
            enc_gemm64(ABUF + (h * 64) * SA + rg * 8, Wt + 4 * cg, acc);
            __syncthreads();
        }
        #pragma unroll
        for (int p = 0; p < 4; p++) {
            float va[4], vb[4];
            #pragma unroll
            for (int c = 0; c < 4; c++) unpack2(acc[p][c], va[c], vb[c]);
            size_t row0 = base + rg * 8 + 2 * p;
            *(float4*)&g_gx[row0 * 384 + pp * 128 + 4 * cg] =
                make_float4(va[0], va[1], va[2], va[3]);
            *(float4*)&g_gx[(row0 + 1) * 384 + pp * 128 + 4 * cg] =
                make_float4(vb[0], vb[1], vb[2], vb[3]);
        }
    }
}

// ---------------------------------------------------------------------------
// GRU scan v2: 128 blocks x 8 rows, 256 threads.
// Thread = (column pair cp, k-quarter kh): lane = (cp&7) + 8*kh, warp = cp>>3.
// Weights in lane-linear smem image wln[(kq*3+g)*256 + tid] (float2 = 2 cols)
// -> conflict-free. h in hT[f][r] stride 12, double-buffered.
// Cross-quarter reduction = warp butterfly shfl (xor 8, xor 16); epilogue
// split across quarters (quarter kh handles rows 2kh, 2kh+1). 1 barrier/step.
// ---------------------------------------------------------------------------
__device__ __forceinline__ ull bfly_sum(ull x) {
    x = add2(x, __shfl_xor_sync(0xffffffffu, x, 8));
    x = add2(x, __shfl_xor_sync(0xffffffffu, x, 16));
    return x;
}
__device__ __forceinline__ ull sel4(ull a0, ull a1, ull a2, ull a3, int kh) {
    ull x = (kh & 1) ? a1 : a0;
    ull y = (kh & 1) ? a3 : a2;
    return (kh & 2) ? y : x;
}

__global__ void __launch_bounds__(256, 1) scan_kernel(
    const float* __restrict__ done, const float* __restrict__ gru0,
    const float* __restrict__ Whh, const float* __restrict__ bhh,
    float* __restrict__ out)
{
    extern __shared__ float sm[];
    float2* wln = (float2*)sm;              // 96*256 float2 = 49152 floats
    float*  hb  = sm + 49152;               // 2 * 1536 floats

    int tid  = threadIdx.x;
    int lane = tid & 31;
    int cp   = (tid >> 5) * 8 + (lane & 7); // 0..63
    int kh   = lane >> 3;                   // 0..3
    int c0   = 2 * cp, c1 = c0 + 1;
    int ra   = 2 * kh, rb = ra + 1;
    int b0   = blockIdx.x << 3;

    // stage weights into lane-linear image
    for (int idx = tid; idx < 96 * 256; idx += 256) {
        int kq = idx / 768;
        int rem = idx - kq * 768;
        int g = rem >> 8, t = rem & 255;
        int cpt = (t >> 5) * 8 + (t & 7);
        int kht = (t & 31) >> 3;
        int k = kht * 32 + kq;
        wln[idx] = make_float2(Whh[(g * 128 + 2 * cpt) * 128 + k],
                               Whh[(g * 128 + 2 * cpt + 1) * 128 + k]);
    }
    // initial h (t=0 mask folded), hT[f][r]
    for (int idx = tid; idx < 1024; idx += 256) {
        int r = idx & 7, f = idx >> 3;
        hb[f * 12 + r] = gru0[(b0 + r) * 128 + f] * (1.f - done[b0 + r]);
    }
    __syncthreads();

    float brv[2] = {bhh[c0], bhh[c1]};
    float bzv[2] = {bhh[128 + c0], bhh[128 + c1]};
    float bnv[2] = {bhh[256 + c0], bhh[256 + c1]};

    // gx regs: [row rr][col cc][gate]
    float gx[2][2][3];
    #pragma unroll
    for (int rr = 0; rr < 2; rr++) {
        size_t row = (size_t)(b0 + ra + rr);
        float2 t0 = *(const float2*)&g_gx[row * 384 + c0];
        float2 t1 = *(const float2*)&g_gx[row * 384 + 128 + c0];
        float2 t2 = *(const float2*)&g_gx[row * 384 + 256 + c0];
        gx[rr][0][0] = t0.x; gx[rr][1][0] = t0.y;
        gx[rr][0][1] = t1.x; gx[rr][1][1] = t1.y;
        gx[rr][0][2] = t2.x; gx[rr][1][2] = t2.y;
    }

    const float2* wp = wln + tid;
    int cur = 0;

    for (int t = 0; t < Tn; t++) {
        // prefetch next gx + done (hidden under k-loop)
        float gxn[2][2][3], dn[2];
        {
            int tnx = (t + 1 < Tn) ? (t + 1) : t;
            #pragma unroll
            for (int rr = 0; rr < 2; rr++) {
                size_t row = (size_t)tnx * Bn + b0 + ra + rr;
                float2 t0 = *(const float2*)&g_gx[row * 384 + c0];
                float2 t1 = *(const float2*)&g_gx[row * 384 + 128 + c0];
                float2 t2 = *(const float2*)&g_gx[row * 384 + 256 + c0];
                gxn[rr][0][0] = t0.x; gxn[rr][1][0] = t0.y;
                gxn[rr][0][1] = t1.x; gxn[rr][1][1] = t1.y;
                gxn[rr][0][2] = t2.x; gxn[rr][1][2] = t2.y;
                dn[rr] = (t + 1 < Tn) ? done[(size_t)(t + 1) * Bn + b0 + ra + rr] : 0.f;
            }
        }

        const float* hbc = hb + cur * 1536;
        const float* hk  = hbc + (kh * 32) * 12;

        ull aR[2][4], aZ[2][4], aN[2][4];
        #pragma unroll
        for (int cc = 0; cc < 2; cc++)
            #pragma unroll
            for (int p = 0; p < 4; p++) { aR[cc][p] = 0; aZ[cc][p] = 0; aN[cc][p] = 0; }

        #pragma unroll 4
        for (int kq = 0; kq < 32; kq++) {
            ulonglong2 hA = *(const ulonglong2*)(hk + kq * 12);      // rows 0-3
            ulonglong2 hB = *(const ulonglong2*)(hk + kq * 12 + 4);  // rows 4-7
            float2 wr = wp[(kq * 3 + 0) * 256];
            float2 wz = wp[(kq * 3 + 1) * 256];
            float2 wn = wp[(kq * 3 + 2) * 256];
            ull wr0 = dup2(wr.x), wr1 = dup2(wr.y);
            ull wz0 = dup2(wz.x), wz1 = dup2(wz.y);
            ull wn0 = dup2(wn.x), wn1 = dup2(wn.y);
            fma2(aR[0][0], hA.x, wr0); fma2(aR[0][1], hA.y, wr0);
            fma2(aR[0][2], hB.x, wr0); fma2(aR[0][3], hB.y, wr0);
            fma2(aR[1][0], hA.x, wr1); fma2(aR[1][1], hA.y, wr1);
            fma2(aR[1][2], hB.x, wr1); fma2(aR[1][3], hB.y, wr1);
            fma2(aZ[0][0], hA.x, wz0); fma2(aZ[0][1], hA.y, wz0);
            fma2(aZ[0][2], hB.x, wz0); fma2(aZ[0][3], hB.y, wz0);
            fma2(aZ[1][0], hA.x, wz1); fma2(aZ[1][1], hA.y, wz1);
            fma2(aZ[1][2], hB.x, wz1); fma2(aZ[1][3], hB.y, wz1);
            fma2(aN[0][0], hA.x, wn0); fma2(aN[0][1], hA.y, wn0);
            fma2(aN[0][2], hB.x, wn0); fma2(aN[0][3], hB.y, wn0);
            fma2(aN[1][0], hA.x, wn1); fma2(aN[1][1], hA.y, wn1);
            fma2(aN[1][2], hB.x, wn1); fma2(aN[1][3], hB.y, wn1);
        }

        // butterfly-reduce across the 4 k-quarters (all lanes get full sums)
        #pragma unroll
        for (int cc = 0; cc < 2; cc++)
            #pragma unroll
            for (int p = 0; p < 4; p++) {
                aR[cc][p] = bfly_sum(aR[cc][p]);
                aZ[cc][p] = bfly_sum(aZ[cc][p]);
                aN[cc][p] = bfly_sum(aN[cc][p]);
            }

        // epilogue: quarter kh handles rows ra, rb
        float sR[2][2], sZ[2][2], sN[2][2];   // [row rr][col cc]
        #pragma unroll
        for (int cc = 0; cc < 2; cc++) {
            float lo, hi;
            unpack2(sel4(aR[cc][0], aR[cc][1], aR[cc][2], aR[cc][3], kh), lo, hi);
            sR[0][cc] = lo; sR[1][cc] = hi;
            unpack2(sel4(aZ[cc][0], aZ[cc][1], aZ[cc][2], aZ[cc][3], kh), lo, hi);
            sZ[0][cc] = lo; sZ[1][cc] = hi;
            unpack2(sel4(aN[cc][0], aN[cc][1], aN[cc][2], aN[cc][3], kh), lo, hi);
            sN[0][cc] = lo; sN[1][cc] = hi;
        }

        float2 hoA = *(const float2*)&hbc[c0 * 12 + ra];   // rows ra,rb col c0
        float2 hoB = *(const float2*)&hbc[c1 * 12 + ra];   // rows ra,rb col c1
        float ho[2][2] = {{hoA.x, hoB.x}, {hoA.y, hoB.y}};

        float hnew[2][2];
        #pragma unroll
        for (int rr = 0; rr < 2; rr++)
            #pragma unroll
            for (int cc = 0; cc < 2; cc++) {
                float sr = sR[rr][cc] + brv[cc] + gx[rr][cc][0];
                float sz = sZ[rr][cc] + bzv[cc] + gx[rr][cc][1];
                float sn = sN[rr][cc] + bnv[cc];
                float rg = sigmoid_fast(sr);
                float zg = sigmoid_fast(sz);
                float ng = tanh_fast(gx[rr][cc][2] + rg * sn);
                hnew[rr][cc] = (1.f - zg) * ng + zg * ho[rr][cc];
            }

        *(float2*)&g_hidden[((size_t)t * Bn + b0 + ra) * Hn + c0] =
            make_float2(hnew[0][0], hnew[0][1]);
        *(float2*)&g_hidden[((size_t)t * Bn + b0 + rb) * Hn + c0] =
            make_float2(hnew[1][0], hnew[1][1]);
        if (t == Tn - 1) {
            *(float2*)&out[(size_t)TBn * 3 + (b0 + ra) * Hn + c0] =
                make_float2(hnew[0][0], hnew[0][1]);
            *(float2*)&out[(size_t)TBn * 3 + (b0 + rb) * Hn + c0] =
                make_float2(hnew[1][0], hnew[1][1]);
        }

        float* hnxt = hb + (cur ^ 1) * 1536;
        *(float2*)&hnxt[c0 * 12 + ra] =
            make_float2(hnew[0][0] * (1.f - dn[0]), hnew[1][0] * (1.f - dn[1]));
        *(float2*)&hnxt[c1 * 12 + ra] =
            make_float2(hnew[0][1] * (1.f - dn[0]), hnew[1][1] * (1.f - dn[1]));

        #pragma unroll
        for (int rr = 0; rr < 2; rr++)
            #pragma unroll
            for (int cc = 0; cc < 2; cc++)
                #pragma unroll
                for (int g = 0; g < 3; g++)
                    gx[rr][cc][g] = gxn[rr][cc][g];

        __syncthreads();
        cur ^= 1;
    }
}

// ---------------------------------------------------------------------------
// Heads (measured-best): thread-per-row, h streamed from global.
// ---------------------------------------------------------------------------
__global__ void __launch_bounds__(512, 4) heads_kernel(
    const int* __restrict__ action,
    const float* __restrict__ Wa, const float* __restrict__ ba,
    const float* __restrict__ Wc, const float* __restrict__ bc,
    float* __restrict__ out)
{
    __shared__ float swa[16 * 128];
    __shared__ float swc[128];
    __shared__ float sba[16];
    __shared__ float sbc;

    int tid = threadIdx.x;
    for (int i = tid; i < 16 * 128; i += 512) swa[i] = Wa[i];
    if (tid < 128) swc[tid] = Wc[tid];
    if (tid < 16)  sba[tid] = ba[tid];
    if (tid == 0)  sbc = bc[0];
    __syncthreads();

    size_t row = (size_t)blockIdx.x * 512 + tid;
    const float* hrow = &g_hidden[row * 128];

    float l[16];
    #pragma unroll
    for (int j = 0; j < 16; j++) l[j] = sba[j];
    float v = sbc;

    #pragma unroll 4
    for (int k4 = 0; k4 < 32; k4++) {
        float4 h4 = *(const float4*)(hrow + k4 * 4);
        const float* wa = &swa[k4 * 4];
        #pragma unroll
        for (int j = 0; j < 16; j++) {
            l[j] += wa[j * 128]     * h4.x;
            l[j] += wa[j * 128 + 1] * h4.y;
            l[j] += wa[j * 128 + 2] * h4.z;
            l[j] += wa[j * 128 + 3] * h4.w;
        }
        v += swc[k4 * 4]     * h4.x + swc[k4 * 4 + 1] * h4.y
           + swc[k4 * 4 + 2] * h4.z + swc[k4 * 4 + 3] * h4.w;
    }

    float mx = l[0];
    #pragma unroll
    for (int j = 1; j < 16; j++) mx = fmaxf(mx, l[j]);
    float se = 0.f, pl = 0.f;
    #pragma unroll
    for (int j = 0; j < 16; j++) {
        float e = __expf(l[j] - mx);
        se += e; pl += e * l[j];
    }
    float lse = mx + __logf(se);
    int a = action[row];
    float la = 0.f;
    #pragma unroll
    for (int j = 0; j < 16; j++) la = (a == j) ? l[j] : la;
    out[row * 3 + 0] = la - lse;
    out[row * 3 + 1] = lse - pl / se;
    out[row * 3 + 2] = v;
}

// ---------------------------------------------------------------------------
extern "C" void kernel_launch(void* const* d_in, const int* in_sizes, int n_in,
                              void* d_out, int out_size)
{
    const float* x    = (const float*)d_in[0];
    const float* done = (const float*)d_in[1];
    const int*   act  = (const int*)  d_in[2];
    const float* gru  = (const float*)d_in[3];
    const float* W1   = (const float*)d_in[4];
    const float* b1   = (const float*)d_in[5];
    const float* W2   = (const float*)d_in[6];
    const float* b2   = (const float*)d_in[7];
    const float* Wih  = (const float*)d_in[8];
    const float* bih  = (const float*)d_in[9];
    const float* Whh  = (const float*)d_in[10];
    const float* bhh  = (const float*)d_in[11];
    const float* Wa   = (const float*)d_in[12];
    const float* ba   = (const float*)d_in[13];
    const float* Wc   = (const float*)d_in[14];
    const float* bc   = (const float*)d_in[15];
    float* out = (float*)d_out;

    size_t enc_smem  = (size_t)(64 * SA + 128 * SA) * sizeof(float);   // 101376 B
    size_t scan_smem = (size_t)(49152 + 2 * 1536) * sizeof(float);     // 208896 B

    cudaFuncSetAttribute(encoder_kernel, cudaFuncAttributeMaxDynamicSharedMemorySize, (int)enc_smem);
    cudaFuncSetAttribute(scan_kernel,    cudaFuncAttributeMaxDynamicSharedMemorySize, (int)scan_smem);

    encoder_kernel<<<TBn / 128, 512, enc_smem>>>(x, W1, b1, W2, b2, Wih, bih);
    scan_kernel<<<128, 256, scan_smem>>>(done, gru, Whh, bhh, out);
    heads_kernel<<<TBn / 512, 512>>>(act, Wa, ba, Wc, bc, out);
}